// round 1
// baseline (speedup 1.0000x reference)
#include <cuda_runtime.h>
#include <cstdint>

#define B_   32768
#define D_   1472
#define E_   8
#define H1_  512
#define H2_  256
#define T_   2
#define NSLAB 32
#define ROWS_PER_SLAB (B_ / NSLAB)   // 1024

// ---------------- scratch (static device allocations; no cudaMalloc) -------
__device__ float g_h1[(size_t)E_ * B_ * H1_];   // 512 MB  pre-BN layer-1 output
__device__ float g_h2[(size_t)E_ * B_ * H2_];   // 256 MB  pre-BN layer-2 output
__device__ float g_gates[(size_t)T_ * B_ * E_]; // 2 MB    softmaxed gates [t][b][e]
__device__ float g_psum[(size_t)E_ * H1_ * NSLAB];
__device__ float g_psq [(size_t)E_ * H1_ * NSLAB];
__device__ float g_s1[E_ * H1_], g_t1[E_ * H1_];
__device__ float g_s2[E_ * H2_], g_t2[E_ * H2_];

// ---------------------------------------------------------------------------
// Gates: gates[t,b,e] = softmax_e( x[b,:] . Wg[t,:,e] + bg[t,e] )
// One warp per row b. Wg is tiny (94 KB) -> lives in L2/L1.
// ---------------------------------------------------------------------------
__global__ __launch_bounds__(256) void gates_kernel(
    const float* __restrict__ X, const float* __restrict__ Wg,
    const float* __restrict__ bg)
{
    int warp = (blockIdx.x * blockDim.x + threadIdx.x) >> 5;
    int lane = threadIdx.x & 31;
    if (warp >= B_) return;
    const float* xr = X + (size_t)warp * D_;

    float acc[16] = {0.f};                      // [t*8 + e]
    for (int d = lane; d < D_; d += 32) {
        float xv = xr[d];
        #pragma unroll
        for (int t = 0; t < T_; ++t) {
            const float* wr = Wg + ((size_t)t * D_ + d) * E_;
            float4 w0 = *(const float4*)wr;
            float4 w1 = *(const float4*)(wr + 4);
            acc[t*8+0] = fmaf(xv, w0.x, acc[t*8+0]);
            acc[t*8+1] = fmaf(xv, w0.y, acc[t*8+1]);
            acc[t*8+2] = fmaf(xv, w0.z, acc[t*8+2]);
            acc[t*8+3] = fmaf(xv, w0.w, acc[t*8+3]);
            acc[t*8+4] = fmaf(xv, w1.x, acc[t*8+4]);
            acc[t*8+5] = fmaf(xv, w1.y, acc[t*8+5]);
            acc[t*8+6] = fmaf(xv, w1.z, acc[t*8+6]);
            acc[t*8+7] = fmaf(xv, w1.w, acc[t*8+7]);
        }
    }
    #pragma unroll
    for (int i = 0; i < 16; ++i)
        #pragma unroll
        for (int o = 16; o > 0; o >>= 1)
            acc[i] += __shfl_xor_sync(0xffffffffu, acc[i], o);

    if (lane == 0) {
        #pragma unroll
        for (int t = 0; t < T_; ++t) {
            float v[8], m = -1e30f;
            #pragma unroll
            for (int e = 0; e < 8; ++e) { v[e] = acc[t*8+e] + bg[t*8+e]; m = fmaxf(m, v[e]); }
            float s = 0.f;
            #pragma unroll
            for (int e = 0; e < 8; ++e) { v[e] = expf(v[e] - m); s += v[e]; }
            float inv = 1.f / s;
            #pragma unroll
            for (int e = 0; e < 8; ++e)
                g_gates[((size_t)t * B_ + warp) * E_ + e] = v[e] * inv;
        }
    }
}

// ---------------------------------------------------------------------------
// GEMM1: g_h1[e,b,h] = x[b,:] . W1[e,:,h] + b1[e,h]
// 128x128x8 tile, 256 threads, 8x8 per thread, fp32.
// ---------------------------------------------------------------------------
__global__ __launch_bounds__(256) void gemm1_kernel(
    const float* __restrict__ X, const float* __restrict__ W1,
    const float* __restrict__ b1)
{
    const int e  = blockIdx.z;
    const int bm = blockIdx.y * 128;
    const int bn = blockIdx.x * 128;
    const float* A  = X  + (size_t)bm * D_;
    const float* Bp = W1 + (size_t)e * D_ * H1_ + bn;

    __shared__ float As[8][128];
    __shared__ float Bs[8][128];

    const int t    = threadIdx.x;
    const int arow = t >> 1, acol = (t & 1) * 4;
    const int brow = t >> 5, bcol = (t & 31) * 4;
    const int tx   = t & 15, ty   = t >> 4;

    float acc[8][8] = {};

    for (int k0 = 0; k0 < D_; k0 += 8) {
        float4 av = *(const float4*)(A + (size_t)arow * D_ + k0 + acol);
        As[acol+0][arow] = av.x;
        As[acol+1][arow] = av.y;
        As[acol+2][arow] = av.z;
        As[acol+3][arow] = av.w;
        *(float4*)&Bs[brow][bcol] =
            *(const float4*)(Bp + (size_t)(k0 + brow) * H1_ + bcol);
        __syncthreads();
        #pragma unroll
        for (int k = 0; k < 8; ++k) {
            float a[8], b[8];
            *(float4*)(a)   = *(const float4*)&As[k][ty*8];
            *(float4*)(a+4) = *(const float4*)&As[k][ty*8+4];
            *(float4*)(b)   = *(const float4*)&Bs[k][tx*8];
            *(float4*)(b+4) = *(const float4*)&Bs[k][tx*8+4];
            #pragma unroll
            for (int i = 0; i < 8; ++i)
                #pragma unroll
                for (int j = 0; j < 8; ++j)
                    acc[i][j] = fmaf(a[i], b[j], acc[i][j]);
        }
        __syncthreads();
    }

    float* C = g_h1 + ((size_t)e * B_ + bm) * H1_ + bn;
    const float* bias = b1 + e * H1_ + bn;
    #pragma unroll
    for (int i = 0; i < 8; ++i) {
        int r = ty*8 + i;
        #pragma unroll
        for (int j = 0; j < 8; j += 4) {
            int c = tx*8 + j;
            float4 v;
            v.x = acc[i][j+0] + bias[c+0];
            v.y = acc[i][j+1] + bias[c+1];
            v.z = acc[i][j+2] + bias[c+2];
            v.w = acc[i][j+3] + bias[c+3];
            *(float4*)(C + (size_t)r * H1_ + c) = v;
        }
    }
}

// ---------------------------------------------------------------------------
// BN stats, deterministic two-stage reduction over the batch axis.
// stats_partial: grid (Hc/64, NSLAB, E), block 256 = 64 cols x 4 rows.
// ---------------------------------------------------------------------------
__global__ __launch_bounds__(256) void stats_partial(int which, int Hc)
{
    const float* F = (which == 0) ? g_h1 : g_h2;
    int e    = blockIdx.z;
    int slab = blockIdx.y;
    int col  = blockIdx.x * 64 + (threadIdx.x & 63);
    int r0   = slab * ROWS_PER_SLAB + (threadIdx.x >> 6);
    int rend = slab * ROWS_PER_SLAB + ROWS_PER_SLAB;

    const float* base = F + (size_t)e * B_ * Hc + col;
    float s = 0.f, q = 0.f;
    for (int r = r0; r < rend; r += 4) {
        float v = base[(size_t)r * Hc];
        s += v; q = fmaf(v, v, q);
    }
    __shared__ float ss[256], sq[256];
    ss[threadIdx.x] = s; sq[threadIdx.x] = q;
    __syncthreads();
    if (threadIdx.x < 128) {
        ss[threadIdx.x] += ss[threadIdx.x + 128];
        sq[threadIdx.x] += sq[threadIdx.x + 128];
    }
    __syncthreads();
    if (threadIdx.x < 64) {
        float fs = ss[threadIdx.x] + ss[threadIdx.x + 64];
        float fq = sq[threadIdx.x] + sq[threadIdx.x + 64];
        size_t idx = ((size_t)(e * Hc + col)) * NSLAB + slab;
        g_psum[idx] = fs; g_psq[idx] = fq;
    }
}

__global__ __launch_bounds__(256) void stats_combine(
    int which, int Hc, const float* __restrict__ gamma,
    const float* __restrict__ beta)
{
    int i = blockIdx.x * 256 + threadIdx.x;
    if (i >= E_ * Hc) return;
    float s = 0.f, q = 0.f;
    for (int j = 0; j < NSLAB; ++j) {
        s += g_psum[(size_t)i * NSLAB + j];
        q += g_psq [(size_t)i * NSLAB + j];
    }
    const float invB = 1.f / (float)B_;
    float mu  = s * invB;
    float var = q * invB - mu * mu;
    float inv = rsqrtf(var + 1e-5f);
    float gg = gamma[i], bb = beta[i];
    float* Sd = (which == 0) ? g_s1 : g_s2;
    float* Td = (which == 0) ? g_t1 : g_t2;
    Sd[i] = gg * inv;
    Td[i] = bb - gg * mu * inv;
}

// ---------------------------------------------------------------------------
// GEMM2: g_h2[e,b,k] = relu(BN1(g_h1[e,b,:])) . W2[e,:,k] + b2[e,k]
// BN1+ReLU applied on the fly while staging the A tile.
// ---------------------------------------------------------------------------
__global__ __launch_bounds__(256) void gemm2_kernel(
    const float* __restrict__ W2, const float* __restrict__ b2)
{
    const int e  = blockIdx.z;
    const int bm = blockIdx.y * 128;
    const int bn = blockIdx.x * 128;
    const float* A  = g_h1 + ((size_t)e * B_ + bm) * H1_;
    const float* Bp = W2 + (size_t)e * H1_ * H2_ + bn;
    const float* S  = g_s1 + e * H1_;
    const float* Tt = g_t1 + e * H1_;

    __shared__ float As[8][128];
    __shared__ float Bs[8][128];

    const int t    = threadIdx.x;
    const int arow = t >> 1, acol = (t & 1) * 4;
    const int brow = t >> 5, bcol = (t & 31) * 4;
    const int tx   = t & 15, ty   = t >> 4;

    float acc[8][8] = {};

    for (int k0 = 0; k0 < H1_; k0 += 8) {
        float4 av = *(const float4*)(A + (size_t)arow * H1_ + k0 + acol);
        float4 sv = *(const float4*)(S  + k0 + acol);
        float4 tv = *(const float4*)(Tt + k0 + acol);
        As[acol+0][arow] = fmaxf(0.f, fmaf(av.x, sv.x, tv.x));
        As[acol+1][arow] = fmaxf(0.f, fmaf(av.y, sv.y, tv.y));
        As[acol+2][arow] = fmaxf(0.f, fmaf(av.z, sv.z, tv.z));
        As[acol+3][arow] = fmaxf(0.f, fmaf(av.w, sv.w, tv.w));
        *(float4*)&Bs[brow][bcol] =
            *(const float4*)(Bp + (size_t)(k0 + brow) * H2_ + bcol);
        __syncthreads();
        #pragma unroll
        for (int k = 0; k < 8; ++k) {
            float a[8], b[8];
            *(float4*)(a)   = *(const float4*)&As[k][ty*8];
            *(float4*)(a+4) = *(const float4*)&As[k][ty*8+4];
            *(float4*)(b)   = *(const float4*)&Bs[k][tx*8];
            *(float4*)(b+4) = *(const float4*)&Bs[k][tx*8+4];
            #pragma unroll
            for (int i = 0; i < 8; ++i)
                #pragma unroll
                for (int j = 0; j < 8; ++j)
                    acc[i][j] = fmaf(a[i], b[j], acc[i][j]);
        }
        __syncthreads();
    }

    float* C = g_h2 + ((size_t)e * B_ + bm) * H2_ + bn;
    const float* bias = b2 + e * H2_ + bn;
    #pragma unroll
    for (int i = 0; i < 8; ++i) {
        int r = ty*8 + i;
        #pragma unroll
        for (int j = 0; j < 8; j += 4) {
            int c = tx*8 + j;
            float4 v;
            v.x = acc[i][j+0] + bias[c+0];
            v.y = acc[i][j+1] + bias[c+1];
            v.z = acc[i][j+2] + bias[c+2];
            v.w = acc[i][j+3] + bias[c+3];
            *(float4*)(C + (size_t)r * H2_ + c) = v;
        }
    }
}

// ---------------------------------------------------------------------------
// Final: out[t,b, e*H2+k] = relu(BN2(g_h2[e,b,k])) * gates[t,b,e]
// One float4 of h2 read -> two float4 outputs (t=0, t=1).
// ---------------------------------------------------------------------------
__global__ __launch_bounds__(256) void final_kernel(float* __restrict__ out)
{
    size_t idx = (size_t)blockIdx.x * blockDim.x + threadIdx.x;  // E*B*(H2/4)
    int k4 = (int)(idx & 63);              // H2/4 = 64
    int b  = (int)((idx >> 6) & (B_ - 1)); // B = 2^15
    int e  = (int)(idx >> 21);
    int k  = k4 * 4;

    float4 h  = *(const float4*)(g_h2 + (((size_t)e * B_ + b) * H2_ + k));
    float4 s  = *(const float4*)(g_s2 + e * H2_ + k);
    float4 tt = *(const float4*)(g_t2 + e * H2_ + k);
    float4 y;
    y.x = fmaxf(0.f, fmaf(h.x, s.x, tt.x));
    y.y = fmaxf(0.f, fmaf(h.y, s.y, tt.y));
    y.z = fmaxf(0.f, fmaf(h.z, s.z, tt.z));
    y.w = fmaxf(0.f, fmaf(h.w, s.w, tt.w));

    float ga = g_gates[(size_t)b * E_ + e];
    float gb = g_gates[(size_t)B_ * E_ + (size_t)b * E_ + e];

    size_t o0 = (size_t)b * (E_ * H2_) + e * H2_ + k;
    size_t o1 = (size_t)B_ * (E_ * H2_) + o0;
    float4 v0 = { y.x * ga, y.y * ga, y.z * ga, y.w * ga };
    float4 v1 = { y.x * gb, y.y * gb, y.z * gb, y.w * gb };
    *(float4*)(out + o0) = v0;
    *(float4*)(out + o1) = v1;
}

// ---------------------------------------------------------------------------
extern "C" void kernel_launch(void* const* d_in, const int* in_sizes, int n_in,
                              void* d_out, int out_size)
{
    const float* x   = (const float*)d_in[0];
    const float* W1  = (const float*)d_in[1];
    const float* b1  = (const float*)d_in[2];
    const float* g1  = (const float*)d_in[3];
    const float* be1 = (const float*)d_in[4];
    const float* W2  = (const float*)d_in[5];
    const float* b2  = (const float*)d_in[6];
    const float* g2  = (const float*)d_in[7];
    const float* be2 = (const float*)d_in[8];
    const float* Wg  = (const float*)d_in[9];
    const float* bg  = (const float*)d_in[10];
    float* out = (float*)d_out;

    gates_kernel<<<B_ / 8, 256>>>(x, Wg, bg);

    gemm1_kernel<<<dim3(H1_ / 128, B_ / 128, E_), 256>>>(x, W1, b1);
    stats_partial<<<dim3(H1_ / 64, NSLAB, E_), 256>>>(0, H1_);
    stats_combine<<<(E_ * H1_ + 255) / 256, 256>>>(0, H1_, g1, be1);

    gemm2_kernel<<<dim3(H2_ / 128, B_ / 128, E_), 256>>>(W2, b2);
    stats_partial<<<dim3(H2_ / 64, NSLAB, E_), 256>>>(1, H2_);
    stats_combine<<<(E_ * H2_ + 255) / 256, 256>>>(1, H2_, g2, be2);

    final_kernel<<<(unsigned)((size_t)E_ * B_ * (H2_ / 4) / 256), 256>>>(out);
}

// round 2
// speedup vs baseline: 2.2857x; 2.2857x over previous
#include <cuda_runtime.h>
#include <cuda_bf16.h>
#include <cstdint>

#define B_   32768
#define D_   1472
#define E_   8
#define H1_  512
#define H2_  256
#define T_   2
#define NSLAB 32
#define ROWS_PER_SLAB (B_ / NSLAB)   // 1024

// ---------------- scratch (static device arrays; no cudaMalloc) ------------
__device__ float g_h1[(size_t)E_ * B_ * H1_];   // 512 MB  pre-BN layer-1 out
__device__ float g_h2[(size_t)E_ * B_ * H2_];   // 256 MB  pre-BN layer-2 out
__device__ float g_gates[(size_t)T_ * B_ * E_];
__device__ float g_psum[(size_t)E_ * H1_ * NSLAB];
__device__ float g_psq [(size_t)E_ * H1_ * NSLAB];
__device__ float g_s1[E_ * H1_], g_t1[E_ * H1_];
__device__ float g_s2[E_ * H2_], g_t2[E_ * H2_];

// ---------------- mma.sync helpers (bf16, m16n8k16) -------------------------
__device__ __forceinline__ uint32_t s2u(const void* p) {
    return (uint32_t)__cvta_generic_to_shared(p);
}
__device__ __forceinline__ void ldsm_x4(uint32_t* r, uint32_t a) {
    asm volatile("ldmatrix.sync.aligned.m8n8.x4.shared.b16 {%0,%1,%2,%3}, [%4];"
        : "=r"(r[0]), "=r"(r[1]), "=r"(r[2]), "=r"(r[3]) : "r"(a));
}
__device__ __forceinline__ void ldsm_x2t(uint32_t* r, uint32_t a) {
    asm volatile("ldmatrix.sync.aligned.m8n8.x2.trans.shared.b16 {%0,%1}, [%2];"
        : "=r"(r[0]), "=r"(r[1]) : "r"(a));
}
__device__ __forceinline__ void mma16816(float* d, const uint32_t* a, const uint32_t* b) {
    asm volatile("mma.sync.aligned.m16n8k16.row.col.f32.bf16.bf16.f32 "
        "{%0,%1,%2,%3}, {%4,%5,%6,%7}, {%8,%9}, {%0,%1,%2,%3};"
        : "+f"(d[0]), "+f"(d[1]), "+f"(d[2]), "+f"(d[3])
        : "r"(a[0]), "r"(a[1]), "r"(a[2]), "r"(a[3]), "r"(b[0]), "r"(b[1]));
}

// split fp32 -> bf16 hi + bf16 lo, packed pairs
__device__ __forceinline__ void split_pair(float x, float y,
                                           __nv_bfloat162& hi, __nv_bfloat162& lo) {
    __nv_bfloat16 hx = __float2bfloat16_rn(x);
    __nv_bfloat16 hy = __float2bfloat16_rn(y);
    __nv_bfloat16 lx = __float2bfloat16_rn(x - __bfloat162float(hx));
    __nv_bfloat16 ly = __float2bfloat16_rn(y - __bfloat162float(hy));
    hi = __halves2bfloat162(hx, hy);
    lo = __halves2bfloat162(lx, ly);
}

#define ASTR 40    // 32 + 8 pad (bf16 elems) -> 80B row stride, ldmatrix conflict-free
#define BSTR 136   // 128 + 8 pad             -> 272B row stride, conflict-free

// ---------------------------------------------------------------------------
// HMMA GEMM with bf16 3-product split.
//  C[e, bm:bm+128, bn:bn+128] = A(e) [128 x K_TOT] * W(e) [K_TOT x N_TOT] + bias
//  ASRC: 0 -> A from param (x_deep, shared across e); 1 -> A = g_h1 (per-e),
//        with BN1+ReLU applied during the smem-staging conversion.
//  CDST: 0 -> g_h1 ; 1 -> g_h2
// ---------------------------------------------------------------------------
template<int K_TOT, int N_TOT, int ASRC, int CDST>
__global__ __launch_bounds__(256, 1) void gemm_hmma(
    const float* __restrict__ Aparam,
    const float* __restrict__ Wall,
    const float* __restrict__ bias_all)
{
    const int e  = blockIdx.z;
    const int bm = blockIdx.y * 128;
    const int bn = blockIdx.x * 128;

    const float* A = (ASRC == 0)
        ? (Aparam + (size_t)bm * K_TOT)
        : (g_h1 + ((size_t)e * B_ + bm) * (size_t)K_TOT);
    const float* W = Wall + ((size_t)e * K_TOT) * N_TOT + bn;
    const float* S  = g_s1 + e * K_TOT;   // only read when ASRC==1
    const float* Tt = g_t1 + e * K_TOT;

    __shared__ alignas(16) __nv_bfloat16 AsH[128 * ASTR];
    __shared__ alignas(16) __nv_bfloat16 AsL[128 * ASTR];
    __shared__ alignas(16) __nv_bfloat16 BsH[32 * BSTR];
    __shared__ alignas(16) __nv_bfloat16 BsL[32 * BSTR];

    const int tid  = threadIdx.x;
    const int lane = tid & 31;
    const int wid  = tid >> 5;
    const int wm   = (wid & 1) * 64;   // 2 warp rows of 64
    const int wn   = (wid >> 1) * 32;  // 4 warp cols of 32

    float acc[4][4][4];
    #pragma unroll
    for (int i = 0; i < 4; ++i)
        #pragma unroll
        for (int j = 0; j < 4; ++j)
            #pragma unroll
            for (int r = 0; r < 4; ++r) acc[i][j][r] = 0.f;

    float4 av[4], bv[4];
    const int NT = K_TOT / 32;

    // initial gmem -> regs
    #pragma unroll
    for (int i = 0; i < 4; ++i) {
        int idx = tid + i * 256;
        av[i] = *(const float4*)(A + (size_t)(idx >> 3) * K_TOT + (idx & 7) * 4);
        bv[i] = *(const float4*)(W + (size_t)(idx >> 5) * N_TOT + (idx & 31) * 4);
    }

    for (int kt = 0; kt < NT; ++kt) {
        // ---- regs -> smem with fp32->bf16 split (and BN1+ReLU for ASRC==1)
        #pragma unroll
        for (int i = 0; i < 4; ++i) {
            int idx = tid + i * 256;
            int row = idx >> 3, c4 = (idx & 7) * 4;
            float4 v = av[i];
            if (ASRC == 1) {
                int kc = kt * 32 + c4;
                float4 s4 = *(const float4*)(S + kc);
                float4 t4 = *(const float4*)(Tt + kc);
                v.x = fmaxf(0.f, fmaf(v.x, s4.x, t4.x));
                v.y = fmaxf(0.f, fmaf(v.y, s4.y, t4.y));
                v.z = fmaxf(0.f, fmaf(v.z, s4.z, t4.z));
                v.w = fmaxf(0.f, fmaf(v.w, s4.w, t4.w));
            }
            __nv_bfloat162 h0, l0, h1, l1;
            split_pair(v.x, v.y, h0, l0);
            split_pair(v.z, v.w, h1, l1);
            int off = row * ASTR + c4;
            *(__nv_bfloat162*)&AsH[off]     = h0;
            *(__nv_bfloat162*)&AsH[off + 2] = h1;
            *(__nv_bfloat162*)&AsL[off]     = l0;
            *(__nv_bfloat162*)&AsL[off + 2] = l1;
        }
        #pragma unroll
        for (int i = 0; i < 4; ++i) {
            int idx = tid + i * 256;
            int row = idx >> 5, c4 = (idx & 31) * 4;
            float4 v = bv[i];
            __nv_bfloat162 h0, l0, h1, l1;
            split_pair(v.x, v.y, h0, l0);
            split_pair(v.z, v.w, h1, l1);
            int off = row * BSTR + c4;
            *(__nv_bfloat162*)&BsH[off]     = h0;
            *(__nv_bfloat162*)&BsH[off + 2] = h1;
            *(__nv_bfloat162*)&BsL[off]     = l0;
            *(__nv_bfloat162*)&BsL[off + 2] = l1;
        }
        __syncthreads();

        // ---- prefetch next tile (gmem latency overlaps the MMAs below)
        if (kt + 1 < NT) {
            #pragma unroll
            for (int i = 0; i < 4; ++i) {
                int idx = tid + i * 256;
                av[i] = *(const float4*)(A + (size_t)(idx >> 3) * K_TOT
                                           + (kt + 1) * 32 + (idx & 7) * 4);
                bv[i] = *(const float4*)(W + (size_t)((kt + 1) * 32 + (idx >> 5)) * N_TOT
                                           + (idx & 31) * 4);
            }
        }

        // ---- MMA on current tile: 2 k-steps of 16
        #pragma unroll
        for (int ks = 0; ks < 2; ++ks) {
            const int k0s = ks * 16;
            uint32_t ah[4][4], al[4][4], bh[4][2], bl[4][2];
            #pragma unroll
            for (int mi = 0; mi < 4; ++mi) {
                int r = wm + mi * 16 + (lane & 15);
                int c = k0s + (lane >> 4) * 8;
                ldsm_x4(ah[mi], s2u(&AsH[r * ASTR + c]));
                ldsm_x4(al[mi], s2u(&AsL[r * ASTR + c]));
            }
            #pragma unroll
            for (int ni = 0; ni < 4; ++ni) {
                int r = k0s + (lane & 15);
                int c = wn + ni * 8;
                ldsm_x2t(bh[ni], s2u(&BsH[r * BSTR + c]));
                ldsm_x2t(bl[ni], s2u(&BsL[r * BSTR + c]));
            }
            #pragma unroll
            for (int mi = 0; mi < 4; ++mi)
                #pragma unroll
                for (int ni = 0; ni < 4; ++ni) {
                    mma16816(acc[mi][ni], ah[mi], bh[ni]);
                    mma16816(acc[mi][ni], ah[mi], bl[ni]);
                    mma16816(acc[mi][ni], al[mi], bh[ni]);
                }
        }
        __syncthreads();
    }

    // ---- epilogue: + bias, fp32 store
    float* C = ((CDST == 0) ? g_h1 : g_h2) + ((size_t)e * B_ + bm) * N_TOT + bn;
    const float* bias = bias_all + e * N_TOT + bn;
    #pragma unroll
    for (int ni = 0; ni < 4; ++ni) {
        int c0 = wn + ni * 8 + (lane & 3) * 2;
        float b0 = bias[c0], b1 = bias[c0 + 1];
        #pragma unroll
        for (int mi = 0; mi < 4; ++mi) {
            int r0 = wm + mi * 16 + (lane >> 2);
            float2 v0 = { acc[mi][ni][0] + b0, acc[mi][ni][1] + b1 };
            float2 v1 = { acc[mi][ni][2] + b0, acc[mi][ni][3] + b1 };
            *(float2*)(C + (size_t)r0 * N_TOT + c0) = v0;
            *(float2*)(C + (size_t)(r0 + 8) * N_TOT + c0) = v1;
        }
    }
}

// ---------------------------------------------------------------------------
// Gates: softmax_e( x . Wg[t] + bg[t] ), one warp per row.
// ---------------------------------------------------------------------------
__global__ __launch_bounds__(256) void gates_kernel(
    const float* __restrict__ X, const float* __restrict__ Wg,
    const float* __restrict__ bg)
{
    int warp = (blockIdx.x * blockDim.x + threadIdx.x) >> 5;
    int lane = threadIdx.x & 31;
    if (warp >= B_) return;
    const float* xr = X + (size_t)warp * D_;

    float acc[16] = {0.f};
    for (int d = lane; d < D_; d += 32) {
        float xv = xr[d];
        #pragma unroll
        for (int t = 0; t < T_; ++t) {
            const float* wr = Wg + ((size_t)t * D_ + d) * E_;
            float4 w0 = *(const float4*)wr;
            float4 w1 = *(const float4*)(wr + 4);
            acc[t*8+0] = fmaf(xv, w0.x, acc[t*8+0]);
            acc[t*8+1] = fmaf(xv, w0.y, acc[t*8+1]);
            acc[t*8+2] = fmaf(xv, w0.z, acc[t*8+2]);
            acc[t*8+3] = fmaf(xv, w0.w, acc[t*8+3]);
            acc[t*8+4] = fmaf(xv, w1.x, acc[t*8+4]);
            acc[t*8+5] = fmaf(xv, w1.y, acc[t*8+5]);
            acc[t*8+6] = fmaf(xv, w1.z, acc[t*8+6]);
            acc[t*8+7] = fmaf(xv, w1.w, acc[t*8+7]);
        }
    }
    #pragma unroll
    for (int i = 0; i < 16; ++i)
        #pragma unroll
        for (int o = 16; o > 0; o >>= 1)
            acc[i] += __shfl_xor_sync(0xffffffffu, acc[i], o);

    if (lane == 0) {
        #pragma unroll
        for (int t = 0; t < T_; ++t) {
            float v[8], m = -1e30f;
            #pragma unroll
            for (int e = 0; e < 8; ++e) { v[e] = acc[t*8+e] + bg[t*8+e]; m = fmaxf(m, v[e]); }
            float s = 0.f;
            #pragma unroll
            for (int e = 0; e < 8; ++e) { v[e] = expf(v[e] - m); s += v[e]; }
            float inv = 1.f / s;
            #pragma unroll
            for (int e = 0; e < 8; ++e)
                g_gates[((size_t)t * B_ + warp) * E_ + e] = v[e] * inv;
        }
    }
}

// ---------------------------------------------------------------------------
// BN stats: deterministic 2-stage reduction over batch.
// ---------------------------------------------------------------------------
__global__ __launch_bounds__(256) void stats_partial(int which, int Hc)
{
    const float* F = (which == 0) ? g_h1 : g_h2;
    int e    = blockIdx.z;
    int slab = blockIdx.y;
    int col  = blockIdx.x * 64 + (threadIdx.x & 63);
    int r0   = slab * ROWS_PER_SLAB + (threadIdx.x >> 6);
    int rend = slab * ROWS_PER_SLAB + ROWS_PER_SLAB;

    const float* base = F + (size_t)e * B_ * Hc + col;
    float s = 0.f, q = 0.f;
    for (int r = r0; r < rend; r += 4) {
        float v = base[(size_t)r * Hc];
        s += v; q = fmaf(v, v, q);
    }
    __shared__ float ss[256], sq[256];
    ss[threadIdx.x] = s; sq[threadIdx.x] = q;
    __syncthreads();
    if (threadIdx.x < 128) {
        ss[threadIdx.x] += ss[threadIdx.x + 128];
        sq[threadIdx.x] += sq[threadIdx.x + 128];
    }
    __syncthreads();
    if (threadIdx.x < 64) {
        float fs = ss[threadIdx.x] + ss[threadIdx.x + 64];
        float fq = sq[threadIdx.x] + sq[threadIdx.x + 64];
        size_t idx = ((size_t)(e * Hc + col)) * NSLAB + slab;
        g_psum[idx] = fs; g_psq[idx] = fq;
    }
}

__global__ __launch_bounds__(256) void stats_combine(
    int which, int Hc, const float* __restrict__ gamma,
    const float* __restrict__ beta)
{
    int i = blockIdx.x * 256 + threadIdx.x;
    if (i >= E_ * Hc) return;
    float s = 0.f, q = 0.f;
    for (int j = 0; j < NSLAB; ++j) {
        s += g_psum[(size_t)i * NSLAB + j];
        q += g_psq [(size_t)i * NSLAB + j];
    }
    const float invB = 1.f / (float)B_;
    float mu  = s * invB;
    float var = q * invB - mu * mu;
    float inv = rsqrtf(var + 1e-5f);
    float gg = gamma[i], bb = beta[i];
    float* Sd = (which == 0) ? g_s1 : g_s2;
    float* Td = (which == 0) ? g_t1 : g_t2;
    Sd[i] = gg * inv;
    Td[i] = bb - gg * mu * inv;
}

// ---------------------------------------------------------------------------
// Final: out[t,b,e*H2+k] = relu(BN2(g_h2[e,b,k])) * gates[t,b,e]
// ---------------------------------------------------------------------------
__global__ __launch_bounds__(256) void final_kernel(float* __restrict__ out)
{
    size_t idx = (size_t)blockIdx.x * blockDim.x + threadIdx.x;
    int k4 = (int)(idx & 63);
    int b  = (int)((idx >> 6) & (B_ - 1));
    int e  = (int)(idx >> 21);
    int k  = k4 * 4;

    float4 h  = *(const float4*)(g_h2 + (((size_t)e * B_ + b) * H2_ + k));
    float4 s  = *(const float4*)(g_s2 + e * H2_ + k);
    float4 tt = *(const float4*)(g_t2 + e * H2_ + k);
    float4 y;
    y.x = fmaxf(0.f, fmaf(h.x, s.x, tt.x));
    y.y = fmaxf(0.f, fmaf(h.y, s.y, tt.y));
    y.z = fmaxf(0.f, fmaf(h.z, s.z, tt.z));
    y.w = fmaxf(0.f, fmaf(h.w, s.w, tt.w));

    float ga = g_gates[(size_t)b * E_ + e];
    float gb = g_gates[(size_t)B_ * E_ + (size_t)b * E_ + e];

    size_t o0 = (size_t)b * (E_ * H2_) + e * H2_ + k;
    size_t o1 = (size_t)B_ * (E_ * H2_) + o0;
    float4 v0 = { y.x * ga, y.y * ga, y.z * ga, y.w * ga };
    float4 v1 = { y.x * gb, y.y * gb, y.z * gb, y.w * gb };
    *(float4*)(out + o0) = v0;
    *(float4*)(out + o1) = v1;
}

// ---------------------------------------------------------------------------
extern "C" void kernel_launch(void* const* d_in, const int* in_sizes, int n_in,
                              void* d_out, int out_size)
{
    const float* x   = (const float*)d_in[0];
    const float* W1  = (const float*)d_in[1];
    const float* b1  = (const float*)d_in[2];
    const float* g1  = (const float*)d_in[3];
    const float* be1 = (const float*)d_in[4];
    const float* W2  = (const float*)d_in[5];
    const float* b2  = (const float*)d_in[6];
    const float* g2  = (const float*)d_in[7];
    const float* be2 = (const float*)d_in[8];
    const float* Wg  = (const float*)d_in[9];
    const float* bg  = (const float*)d_in[10];
    float* out = (float*)d_out;

    gates_kernel<<<B_ / 8, 256>>>(x, Wg, bg);

    gemm_hmma<D_, H1_, 0, 0><<<dim3(H1_ / 128, B_ / 128, E_), 256>>>(x, W1, b1);
    stats_partial<<<dim3(H1_ / 64, NSLAB, E_), 256>>>(0, H1_);
    stats_combine<<<(E_ * H1_ + 255) / 256, 256>>>(0, H1_, g1, be1);

    gemm_hmma<H1_, H2_, 1, 1><<<dim3(H2_ / 128, B_ / 128, E_), 256>>>(nullptr, W2, b2);
    stats_partial<<<dim3(H2_ / 64, NSLAB, E_), 256>>>(1, H2_);
    stats_combine<<<(E_ * H2_ + 255) / 256, 256>>>(1, H2_, g2, be2);

    final_kernel<<<(unsigned)((size_t)E_ * B_ * (H2_ / 4) / 256), 256>>>(out);
}

// round 4
// speedup vs baseline: 2.3411x; 1.0243x over previous
#include <cuda_runtime.h>
#include <cuda_bf16.h>
#include <cstdint>

#define B_   32768
#define D_   1472
#define E_   8
#define H1_  512
#define H2_  256
#define T_   2
#define NSLAB 32
#define ROWS_PER_SLAB (B_ / NSLAB)   // 1024

// ---------------- scratch (static device arrays; no cudaMalloc) ------------
__device__ float g_h1[(size_t)E_ * B_ * H1_];   // 512 MB  pre-BN layer-1 out
__device__ float g_h2[(size_t)E_ * B_ * H2_];   // 256 MB  pre-BN layer-2 out
__device__ float g_gates[(size_t)T_ * B_ * E_];
__device__ float g_psum[(size_t)E_ * H1_ * NSLAB];
__device__ float g_psq [(size_t)E_ * H1_ * NSLAB];
__device__ float g_s1[E_ * H1_], g_t1[E_ * H1_];
__device__ float g_s2[E_ * H2_], g_t2[E_ * H2_];
// bf16 hi/lo pre-splits (same layout as fp32 originals)
__device__ __nv_bfloat16 g_xh[(size_t)B_ * D_];          // 96 MB
__device__ __nv_bfloat16 g_xl[(size_t)B_ * D_];
__device__ __nv_bfloat16 g_w1h[(size_t)E_ * D_ * H1_];   // 12 MB
__device__ __nv_bfloat16 g_w1l[(size_t)E_ * D_ * H1_];
__device__ __nv_bfloat16 g_w2h[(size_t)E_ * H1_ * H2_];  // 2 MB
__device__ __nv_bfloat16 g_w2l[(size_t)E_ * H1_ * H2_];

// ---------------- PTX helpers ----------------------------------------------
__device__ __forceinline__ uint32_t s2u(const void* p) {
    return (uint32_t)__cvta_generic_to_shared(p);
}
__device__ __forceinline__ void ldsm_x4(uint32_t* r, uint32_t a) {
    asm volatile("ldmatrix.sync.aligned.m8n8.x4.shared.b16 {%0,%1,%2,%3}, [%4];"
        : "=r"(r[0]), "=r"(r[1]), "=r"(r[2]), "=r"(r[3]) : "r"(a));
}
__device__ __forceinline__ void ldsm_x2t(uint32_t* r, uint32_t a) {
    asm volatile("ldmatrix.sync.aligned.m8n8.x2.trans.shared.b16 {%0,%1}, [%2];"
        : "=r"(r[0]), "=r"(r[1]) : "r"(a));
}
__device__ __forceinline__ void mma16816(float* d, const uint32_t* a, const uint32_t* b) {
    asm volatile("mma.sync.aligned.m16n8k16.row.col.f32.bf16.bf16.f32 "
        "{%0,%1,%2,%3}, {%4,%5,%6,%7}, {%8,%9}, {%0,%1,%2,%3};"
        : "+f"(d[0]), "+f"(d[1]), "+f"(d[2]), "+f"(d[3])
        : "r"(a[0]), "r"(a[1]), "r"(a[2]), "r"(a[3]), "r"(b[0]), "r"(b[1]));
}
__device__ __forceinline__ void cp16(uint32_t dst, const void* src) {
    asm volatile("cp.async.cg.shared.global [%0], [%1], 16;"
        :: "r"(dst), "l"(src) : "memory");
}
__device__ __forceinline__ void cp_commit() {
    asm volatile("cp.async.commit_group;" ::: "memory");
}
__device__ __forceinline__ void cp_wait0() {
    asm volatile("cp.async.wait_group 0;" ::: "memory");
}

__device__ __forceinline__ void split_pair(float x, float y,
                                           uint32_t& hi, uint32_t& lo) {
    __nv_bfloat16 hx = __float2bfloat16_rn(x);
    __nv_bfloat16 hy = __float2bfloat16_rn(y);
    __nv_bfloat16 lx = __float2bfloat16_rn(x - __bfloat162float(hx));
    __nv_bfloat16 ly = __float2bfloat16_rn(y - __bfloat162float(hy));
    __nv_bfloat162 h = __halves2bfloat162(hx, hy);
    __nv_bfloat162 l = __halves2bfloat162(lx, ly);
    hi = *reinterpret_cast<uint32_t*>(&h);
    lo = *reinterpret_cast<uint32_t*>(&l);
}

// ---------------- SMEM layout (bytes) ---------------------------------------
// A tiles: 128 rows x 32 bf16, padded row = 40 elems (80 B)  -> 10240 B
// B tiles: 32 rows x 128 bf16, padded row = 136 elems (272B) -> 8704 B
#define ASTR 40
#define BSTR 136
#define STG_SZ 37888
#define AH_(b) ((b) * STG_SZ)
#define AL_(b) ((b) * STG_SZ + 10240)
#define BH_(b) ((b) * STG_SZ + 20480)
#define BL_(b) ((b) * STG_SZ + 29184)
#define SMEM_BYTES (2 * STG_SZ)   // 75776

// ---------------------------------------------------------------------------
// Double-buffered cp.async HMMA GEMM, bf16 3-product split.
//  ASRC 0: A = pre-split x (g_xh/g_xl), C -> g_h1, W -> g_w1h/l
//  ASRC 1: A = relu(BN1(g_h1)) fused during staging, C -> g_h2, W -> g_w2h/l
//  NB: n-blocks per expert (grid.x = NB * E_), for L2-friendly ordering.
// ---------------------------------------------------------------------------
template<int K_TOT, int N_TOT, int ASRC, int NB>
__global__ __launch_bounds__(256, 1) void gemm_hmma(
    const float* __restrict__ bias_all)
{
    extern __shared__ char smem[];
    const uint32_t sb = s2u(smem);
    const int tid  = threadIdx.x;
    const int lane = tid & 31;
    const int wid  = tid >> 5;
    const int wm   = (wid & 1) * 64;
    const int wn   = (wid >> 1) * 32;

    const int e  = blockIdx.x / NB;
    const int bn = (blockIdx.x % NB) * 128;
    const int bm = blockIdx.y * 128;

    const __nv_bfloat16* Ah = g_xh + (size_t)bm * K_TOT;          // ASRC==0
    const __nv_bfloat16* Al = g_xl + (size_t)bm * K_TOT;
    const float* Af = g_h1 + ((size_t)e * B_ + bm) * (size_t)K_TOT; // ASRC==1
    const __nv_bfloat16* Wh =
        ((ASRC == 0) ? g_w1h : g_w2h) + (size_t)e * K_TOT * N_TOT + bn;
    const __nv_bfloat16* Wl =
        ((ASRC == 0) ? g_w1l : g_w2l) + (size_t)e * K_TOT * N_TOT + bn;
    const float* S  = g_s1 + e * K_TOT;
    const float* Tt = g_t1 + e * K_TOT;

    float acc[4][4][4];
    #pragma unroll
    for (int i = 0; i < 4; ++i)
        #pragma unroll
        for (int j = 0; j < 4; ++j)
            #pragma unroll
            for (int r = 0; r < 4; ++r) acc[i][j][r] = 0.f;

    constexpr int NT = K_TOT / 32;
    float4 av[4];   // ASRC==1 register staging

    // ---- prefetch stage 0
    if (ASRC == 0) {
        #pragma unroll
        for (int i = 0; i < 4; ++i) {
            int c = tid + i * 256, cc = c & 511;
            int row = cc >> 2, k4 = cc & 3;
            const __nv_bfloat16* src = ((c < 512) ? Ah : Al)
                                       + (size_t)row * K_TOT + k4 * 8;
            cp16(sb + ((c < 512) ? AH_(0) : AL_(0)) + row * 80 + k4 * 16, src);
        }
    } else {
        #pragma unroll
        for (int i = 0; i < 4; ++i) {
            int idx = tid + i * 256;
            av[i] = *(const float4*)(Af + (size_t)(idx >> 3) * K_TOT + (idx & 7) * 4);
        }
    }
    #pragma unroll
    for (int i = 0; i < 4; ++i) {
        int c = tid + i * 256, cc = c & 511;
        int kr = cc >> 4, n16 = cc & 15;
        const __nv_bfloat16* src = ((c < 512) ? Wh : Wl)
                                   + (size_t)kr * N_TOT + n16 * 8;
        cp16(sb + ((c < 512) ? BH_(0) : BL_(0)) + kr * 272 + n16 * 16, src);
    }
    cp_commit();

    for (int kt = 0; kt < NT; ++kt) {
        const int cur = kt & 1;

        if (ASRC == 1) {
            // convert prefetched regs -> smem A tile (BN1 + ReLU + split)
            __nv_bfloat16* aH = (__nv_bfloat16*)(smem + AH_(cur));
            __nv_bfloat16* aL = (__nv_bfloat16*)(smem + AL_(cur));
            #pragma unroll
            for (int i = 0; i < 4; ++i) {
                int idx = tid + i * 256;
                int row = idx >> 3, c4 = (idx & 7) * 4;
                float4 v = av[i];
                int kc = kt * 32 + c4;
                float4 s4 = *(const float4*)(S + kc);
                float4 t4 = *(const float4*)(Tt + kc);
                v.x = fmaxf(0.f, fmaf(v.x, s4.x, t4.x));
                v.y = fmaxf(0.f, fmaf(v.y, s4.y, t4.y));
                v.z = fmaxf(0.f, fmaf(v.z, s4.z, t4.z));
                v.w = fmaxf(0.f, fmaf(v.w, s4.w, t4.w));
                uint32_t h0, l0, h1, l1;
                split_pair(v.x, v.y, h0, l0);
                split_pair(v.z, v.w, h1, l1);
                int off = row * ASTR + c4;
                *(uint32_t*)&aH[off]     = h0;
                *(uint32_t*)&aH[off + 2] = h1;
                *(uint32_t*)&aL[off]     = l0;
                *(uint32_t*)&aL[off + 2] = l1;
            }
        }

        cp_wait0();
        __syncthreads();

        // ---- prefetch stage kt+1 (overlaps the MMA block below)
        if (kt + 1 < NT) {
            const int nxt = (kt + 1) & 1;
            const int k0n = (kt + 1) * 32;
            if (ASRC == 0) {
                #pragma unroll
                for (int i = 0; i < 4; ++i) {
                    int c = tid + i * 256, cc = c & 511;
                    int row = cc >> 2, k4 = cc & 3;
                    const __nv_bfloat16* src = ((c < 512) ? Ah : Al)
                        + (size_t)row * K_TOT + k0n + k4 * 8;
                    cp16(sb + ((c < 512) ? AH_(nxt) : AL_(nxt)) + row * 80 + k4 * 16, src);
                }
            } else {
                #pragma unroll
                for (int i = 0; i < 4; ++i) {
                    int idx = tid + i * 256;
                    av[i] = *(const float4*)(Af + (size_t)(idx >> 3) * K_TOT
                                               + k0n + (idx & 7) * 4);
                }
            }
            #pragma unroll
            for (int i = 0; i < 4; ++i) {
                int c = tid + i * 256, cc = c & 511;
                int kr = cc >> 4, n16 = cc & 15;
                const __nv_bfloat16* src = ((c < 512) ? Wh : Wl)
                    + (size_t)(k0n + kr) * N_TOT + n16 * 8;
                cp16(sb + ((c < 512) ? BH_(nxt) : BL_(nxt)) + kr * 272 + n16 * 16, src);
            }
            cp_commit();
        }

        // ---- MMAs on stage cur
        const __nv_bfloat16* aH = (const __nv_bfloat16*)(smem + AH_(cur));
        const __nv_bfloat16* aL = (const __nv_bfloat16*)(smem + AL_(cur));
        const __nv_bfloat16* bH = (const __nv_bfloat16*)(smem + BH_(cur));
        const __nv_bfloat16* bL = (const __nv_bfloat16*)(smem + BL_(cur));
        #pragma unroll
        for (int ks = 0; ks < 2; ++ks) {
            const int k0s = ks * 16;
            uint32_t ah[4][4], al[4][4], bh[4][2], bl[4][2];
            #pragma unroll
            for (int mi = 0; mi < 4; ++mi) {
                int r = wm + mi * 16 + (lane & 15);
                int c = k0s + (lane >> 4) * 8;
                ldsm_x4(ah[mi], s2u(&aH[r * ASTR + c]));
                ldsm_x4(al[mi], s2u(&aL[r * ASTR + c]));
            }
            #pragma unroll
            for (int ni = 0; ni < 4; ++ni) {
                int r = k0s + (lane & 15);
                int c = wn + ni * 8;
                ldsm_x2t(bh[ni], s2u(&bH[r * BSTR + c]));
                ldsm_x2t(bl[ni], s2u(&bL[r * BSTR + c]));
            }
            #pragma unroll
            for (int mi = 0; mi < 4; ++mi)
                #pragma unroll
                for (int ni = 0; ni < 4; ++ni) {
                    mma16816(acc[mi][ni], ah[mi], bh[ni]);
                    mma16816(acc[mi][ni], ah[mi], bl[ni]);
                    mma16816(acc[mi][ni], al[mi], bh[ni]);
                }
        }
        __syncthreads();
    }

    // ---- epilogue: + bias, fp32 store
    float* C = ((ASRC == 0) ? g_h1 : g_h2) + ((size_t)e * B_ + bm) * N_TOT + bn;
    const float* bias = bias_all + e * N_TOT + bn;
    #pragma unroll
    for (int ni = 0; ni < 4; ++ni) {
        int c0 = wn + ni * 8 + (lane & 3) * 2;
        float b0 = bias[c0], b1 = bias[c0 + 1];
        #pragma unroll
        for (int mi = 0; mi < 4; ++mi) {
            int r0 = wm + mi * 16 + (lane >> 2);
            float2 v0 = { acc[mi][ni][0] + b0, acc[mi][ni][1] + b1 };
            float2 v1 = { acc[mi][ni][2] + b0, acc[mi][ni][3] + b1 };
            *(float2*)(C + (size_t)r0 * N_TOT + c0) = v0;
            *(float2*)(C + (size_t)(r0 + 8) * N_TOT + c0) = v1;
        }
    }
}

// ---------------------------------------------------------------------------
// fp32 -> bf16 hi/lo split over a flat array (8 elems / thread)
// ---------------------------------------------------------------------------
__global__ __launch_bounds__(256) void split_arr(
    const float* __restrict__ src, __nv_bfloat16* __restrict__ dh,
    __nv_bfloat16* __restrict__ dl, size_t n8)
{
    size_t i = (size_t)blockIdx.x * 256 + threadIdx.x;
    if (i >= n8) return;
    const float4* s = (const float4*)src + i * 2;
    float4 v0 = s[0], v1 = s[1];
    uint4 h, l;
    split_pair(v0.x, v0.y, h.x, l.x);
    split_pair(v0.z, v0.w, h.y, l.y);
    split_pair(v1.x, v1.y, h.z, l.z);
    split_pair(v1.z, v1.w, h.w, l.w);
    ((uint4*)dh)[i] = h;
    ((uint4*)dl)[i] = l;
}

// ---------------------------------------------------------------------------
// Gates: softmax_e( x . Wg[t] + bg[t] ), one warp per row.
// ---------------------------------------------------------------------------
__global__ __launch_bounds__(256) void gates_kernel(
    const float* __restrict__ X, const float* __restrict__ Wg,
    const float* __restrict__ bg)
{
    int warp = (blockIdx.x * blockDim.x + threadIdx.x) >> 5;
    int lane = threadIdx.x & 31;
    if (warp >= B_) return;
    const float* xr = X + (size_t)warp * D_;

    float acc[16] = {0.f};
    for (int d = lane; d < D_; d += 32) {
        float xv = xr[d];
        #pragma unroll
        for (int t = 0; t < T_; ++t) {
            const float* wr = Wg + ((size_t)t * D_ + d) * E_;
            float4 w0 = *(const float4*)wr;
            float4 w1 = *(const float4*)(wr + 4);
            acc[t*8+0] = fmaf(xv, w0.x, acc[t*8+0]);
            acc[t*8+1] = fmaf(xv, w0.y, acc[t*8+1]);
            acc[t*8+2] = fmaf(xv, w0.z, acc[t*8+2]);
            acc[t*8+3] = fmaf(xv, w0.w, acc[t*8+3]);
            acc[t*8+4] = fmaf(xv, w1.x, acc[t*8+4]);
            acc[t*8+5] = fmaf(xv, w1.y, acc[t*8+5]);
            acc[t*8+6] = fmaf(xv, w1.z, acc[t*8+6]);
            acc[t*8+7] = fmaf(xv, w1.w, acc[t*8+7]);
        }
    }
    #pragma unroll
    for (int i = 0; i < 16; ++i)
        #pragma unroll
        for (int o = 16; o > 0; o >>= 1)
            acc[i] += __shfl_xor_sync(0xffffffffu, acc[i], o);

    if (lane == 0) {
        #pragma unroll
        for (int t = 0; t < T_; ++t) {
            float v[8], m = -1e30f;
            #pragma unroll
            for (int e = 0; e < 8; ++e) { v[e] = acc[t*8+e] + bg[t*8+e]; m = fmaxf(m, v[e]); }
            float s = 0.f;
            #pragma unroll
            for (int e = 0; e < 8; ++e) { v[e] = expf(v[e] - m); s += v[e]; }
            float inv = 1.f / s;
            #pragma unroll
            for (int e = 0; e < 8; ++e)
                g_gates[((size_t)t * B_ + warp) * E_ + e] = v[e] * inv;
        }
    }
}

// ---------------------------------------------------------------------------
// BN stats: deterministic 2-stage reduction over batch.
// ---------------------------------------------------------------------------
__global__ __launch_bounds__(256) void stats_partial(int which, int Hc)
{
    const float* F = (which == 0) ? g_h1 : g_h2;
    int e    = blockIdx.z;
    int slab = blockIdx.y;
    int col  = blockIdx.x * 64 + (threadIdx.x & 63);
    int r0   = slab * ROWS_PER_SLAB + (threadIdx.x >> 6);
    int rend = slab * ROWS_PER_SLAB + ROWS_PER_SLAB;

    const float* base = F + (size_t)e * B_ * Hc + col;
    float s = 0.f, q = 0.f;
    for (int r = r0; r < rend; r += 4) {
        float v = base[(size_t)r * Hc];
        s += v; q = fmaf(v, v, q);
    }
    __shared__ float ss[256], sq[256];
    ss[threadIdx.x] = s; sq[threadIdx.x] = q;
    __syncthreads();
    if (threadIdx.x < 128) {
        ss[threadIdx.x] += ss[threadIdx.x + 128];
        sq[threadIdx.x] += sq[threadIdx.x + 128];
    }
    __syncthreads();
    if (threadIdx.x < 64) {
        float fs = ss[threadIdx.x] + ss[threadIdx.x + 64];
        float fq = sq[threadIdx.x] + sq[threadIdx.x + 64];
        size_t idx = ((size_t)(e * Hc + col)) * NSLAB + slab;
        g_psum[idx] = fs; g_psq[idx] = fq;
    }
}

__global__ __launch_bounds__(256) void stats_combine(
    int which, int Hc, const float* __restrict__ gamma,
    const float* __restrict__ beta)
{
    int i = blockIdx.x * 256 + threadIdx.x;
    if (i >= E_ * Hc) return;
    float s = 0.f, q = 0.f;
    for (int j = 0; j < NSLAB; ++j) {
        s += g_psum[(size_t)i * NSLAB + j];
        q += g_psq [(size_t)i * NSLAB + j];
    }
    const float invB = 1.f / (float)B_;
    float mu  = s * invB;
    float var = q * invB - mu * mu;
    float inv = rsqrtf(var + 1e-5f);
    float gg = gamma[i], bb = beta[i];
    float* Sd = (which == 0) ? g_s1 : g_s2;
    float* Td = (which == 0) ? g_t1 : g_t2;
    Sd[i] = gg * inv;
    Td[i] = bb - gg * mu * inv;
}

// ---------------------------------------------------------------------------
// Final: out[t,b,e*H2+k] = relu(BN2(g_h2[e,b,k])) * gates[t,b,e]
// ---------------------------------------------------------------------------
__global__ __launch_bounds__(256) void final_kernel(float* __restrict__ out)
{
    size_t idx = (size_t)blockIdx.x * blockDim.x + threadIdx.x;
    int k4 = (int)(idx & 63);
    int b  = (int)((idx >> 6) & (B_ - 1));
    int e  = (int)(idx >> 21);
    int k  = k4 * 4;

    float4 h  = *(const float4*)(g_h2 + (((size_t)e * B_ + b) * H2_ + k));
    float4 s  = *(const float4*)(g_s2 + e * H2_ + k);
    float4 tt = *(const float4*)(g_t2 + e * H2_ + k);
    float4 y;
    y.x = fmaxf(0.f, fmaf(h.x, s.x, tt.x));
    y.y = fmaxf(0.f, fmaf(h.y, s.y, tt.y));
    y.z = fmaxf(0.f, fmaf(h.z, s.z, tt.z));
    y.w = fmaxf(0.f, fmaf(h.w, s.w, tt.w));

    float ga = g_gates[(size_t)b * E_ + e];
    float gb = g_gates[(size_t)B_ * E_ + (size_t)b * E_ + e];

    size_t o0 = (size_t)b * (E_ * H2_) + e * H2_ + k;
    size_t o1 = (size_t)B_ * (E_ * H2_) + o0;
    float4 v0 = { y.x * ga, y.y * ga, y.z * ga, y.w * ga };
    float4 v1 = { y.x * gb, y.y * gb, y.z * gb, y.w * gb };
    *(float4*)(out + o0) = v0;
    *(float4*)(out + o1) = v1;
}

// ---------------------------------------------------------------------------
extern "C" void kernel_launch(void* const* d_in, const int* in_sizes, int n_in,
                              void* d_out, int out_size)
{
    const float* x   = (const float*)d_in[0];
    const float* W1  = (const float*)d_in[1];
    const float* b1  = (const float*)d_in[2];
    const float* g1  = (const float*)d_in[3];
    const float* be1 = (const float*)d_in[4];
    const float* W2  = (const float*)d_in[5];
    const float* b2  = (const float*)d_in[6];
    const float* g2  = (const float*)d_in[7];
    const float* be2 = (const float*)d_in[8];
    const float* Wg  = (const float*)d_in[9];
    const float* bg  = (const float*)d_in[10];
    float* out = (float*)d_out;

    cudaFuncSetAttribute(gemm_hmma<D_, H1_, 0, 4>,
        cudaFuncAttributeMaxDynamicSharedMemorySize, SMEM_BYTES);
    cudaFuncSetAttribute(gemm_hmma<H1_, H2_, 1, 2>,
        cudaFuncAttributeMaxDynamicSharedMemorySize, SMEM_BYTES);

    // ---- pre-splits
    {
        __nv_bfloat16 *xh, *xl, *w1h, *w1l, *w2h, *w2l;
        cudaGetSymbolAddress((void**)&xh,  g_xh);
        cudaGetSymbolAddress((void**)&xl,  g_xl);
        cudaGetSymbolAddress((void**)&w1h, g_w1h);
        cudaGetSymbolAddress((void**)&w1l, g_w1l);
        cudaGetSymbolAddress((void**)&w2h, g_w2h);
        cudaGetSymbolAddress((void**)&w2l, g_w2l);
        size_t nx = (size_t)B_ * D_ / 8;
        size_t n1 = (size_t)E_ * D_ * H1_ / 8;
        size_t n2 = (size_t)E_ * H1_ * H2_ / 8;
        split_arr<<<(unsigned)((nx + 255) / 256), 256>>>(x,  xh,  xl,  nx);
        split_arr<<<(unsigned)((n1 + 255) / 256), 256>>>(W1, w1h, w1l, n1);
        split_arr<<<(unsigned)((n2 + 255) / 256), 256>>>(W2, w2h, w2l, n2);
    }

    gates_kernel<<<B_ / 8, 256>>>(x, Wg, bg);

    gemm_hmma<D_, H1_, 0, 4>
        <<<dim3(4 * E_, B_ / 128), 256, SMEM_BYTES>>>(b1);
    stats_partial<<<dim3(H1_ / 64, NSLAB, E_), 256>>>(0, H1_);
    stats_combine<<<(E_ * H1_ + 255) / 256, 256>>>(0, H1_, g1, be1);

    gemm_hmma<H1_, H2_, 1, 2>
        <<<dim3(2 * E_, B_ / 128), 256, SMEM_BYTES>>>(b2);
    stats_partial<<<dim3(H2_ / 64, NSLAB, E_), 256>>>(1, H2_);
    stats_combine<<<(E_ * H2_ + 255) / 256, 256>>>(1, H2_, g2, be2);

    final_kernel<<<(unsigned)((size_t)E_ * B_ * (H2_ / 4) / 256), 256>>>(out);
}

// round 5
// speedup vs baseline: 2.8825x; 1.2313x over previous
#include <cuda_runtime.h>
#include <cuda_bf16.h>
#include <cstdint>

#define B_   32768
#define D_   1472
#define E_   8
#define H1_  512
#define H2_  256
#define T_   2
#define NSLAB 256          // one stats slab per 128-row m-block

// ---------------- scratch (static device arrays; no cudaMalloc) ------------
__device__ float g_h1[(size_t)E_ * B_ * H1_];
__device__ float g_h2[(size_t)E_ * B_ * H2_];
__device__ float g_gates[(size_t)T_ * B_ * E_];
__device__ float g_psum[(size_t)E_ * H1_ * NSLAB];   // 4 MB
__device__ float g_psq [(size_t)E_ * H1_ * NSLAB];
__device__ float g_s1[E_ * H1_], g_t1[E_ * H1_];
__device__ float g_s2[E_ * H2_], g_t2[E_ * H2_];
// bf16 hi/lo pre-splits (same layout as fp32 originals)
__device__ __nv_bfloat16 g_xh[(size_t)B_ * D_];
__device__ __nv_bfloat16 g_xl[(size_t)B_ * D_];
__device__ __nv_bfloat16 g_w1h[(size_t)E_ * D_ * H1_];
__device__ __nv_bfloat16 g_w1l[(size_t)E_ * D_ * H1_];
__device__ __nv_bfloat16 g_w2h[(size_t)E_ * H1_ * H2_];
__device__ __nv_bfloat16 g_w2l[(size_t)E_ * H1_ * H2_];

// ---------------- PTX helpers ----------------------------------------------
__device__ __forceinline__ uint32_t s2u(const void* p) {
    return (uint32_t)__cvta_generic_to_shared(p);
}
__device__ __forceinline__ void ldsm_x4(uint32_t* r, uint32_t a) {
    asm volatile("ldmatrix.sync.aligned.m8n8.x4.shared.b16 {%0,%1,%2,%3}, [%4];"
        : "=r"(r[0]), "=r"(r[1]), "=r"(r[2]), "=r"(r[3]) : "r"(a));
}
__device__ __forceinline__ void ldsm_x4t(uint32_t* r, uint32_t a) {
    asm volatile("ldmatrix.sync.aligned.m8n8.x4.trans.shared.b16 {%0,%1,%2,%3}, [%4];"
        : "=r"(r[0]), "=r"(r[1]), "=r"(r[2]), "=r"(r[3]) : "r"(a));
}
__device__ __forceinline__ void mma16816(float* d, const uint32_t* a, const uint32_t* b) {
    asm volatile("mma.sync.aligned.m16n8k16.row.col.f32.bf16.bf16.f32 "
        "{%0,%1,%2,%3}, {%4,%5,%6,%7}, {%8,%9}, {%0,%1,%2,%3};"
        : "+f"(d[0]), "+f"(d[1]), "+f"(d[2]), "+f"(d[3])
        : "r"(a[0]), "r"(a[1]), "r"(a[2]), "r"(a[3]), "r"(b[0]), "r"(b[1]));
}
__device__ __forceinline__ void cp16(uint32_t dst, const void* src) {
    asm volatile("cp.async.cg.shared.global [%0], [%1], 16;"
        :: "r"(dst), "l"(src) : "memory");
}
__device__ __forceinline__ void cp_commit() {
    asm volatile("cp.async.commit_group;" ::: "memory");
}
__device__ __forceinline__ void cp_wait0() {
    asm volatile("cp.async.wait_group 0;" ::: "memory");
}

__device__ __forceinline__ void split_pair(float x, float y,
                                           uint32_t& hi, uint32_t& lo) {
    __nv_bfloat16 hx = __float2bfloat16_rn(x);
    __nv_bfloat16 hy = __float2bfloat16_rn(y);
    __nv_bfloat16 lx = __float2bfloat16_rn(x - __bfloat162float(hx));
    __nv_bfloat16 ly = __float2bfloat16_rn(y - __bfloat162float(hy));
    __nv_bfloat162 h = __halves2bfloat162(hx, hy);
    __nv_bfloat162 l = __halves2bfloat162(lx, ly);
    hi = *reinterpret_cast<uint32_t*>(&h);
    lo = *reinterpret_cast<uint32_t*>(&l);
}

// ---------------- SMEM layout (bytes) ---------------------------------------
#define ASTR 40
#define BSTR 136
#define STG_SZ 37888
#define AH_(b) ((b) * STG_SZ)
#define AL_(b) ((b) * STG_SZ + 10240)
#define BH_(b) ((b) * STG_SZ + 20480)
#define BL_(b) ((b) * STG_SZ + 29184)
#define SMEM_BYTES (2 * STG_SZ)   // 75776

// ---------------------------------------------------------------------------
// Double-buffered cp.async HMMA GEMM, bf16 3-product split, 2 CTAs/SM,
// BN batch-stats (sum, sum-sq of acc+bias) fused into the epilogue.
// ---------------------------------------------------------------------------
template<int K_TOT, int N_TOT, int ASRC, int NB>
__global__ __launch_bounds__(256, 2) void gemm_hmma(
    const float* __restrict__ bias_all)
{
    extern __shared__ char smem[];
    __shared__ float sred_s[2][128];
    __shared__ float sred_q[2][128];
    const uint32_t sb = s2u(smem);
    const int tid  = threadIdx.x;
    const int lane = tid & 31;
    const int wid  = tid >> 5;
    const int wm   = (wid & 1) * 64;
    const int wn   = (wid >> 1) * 32;

    const int e  = blockIdx.x / NB;
    const int bn = (blockIdx.x % NB) * 128;
    const int bm = blockIdx.y * 128;

    const __nv_bfloat16* Ah = g_xh + (size_t)bm * K_TOT;            // ASRC==0
    const __nv_bfloat16* Al = g_xl + (size_t)bm * K_TOT;
    const float* Af = g_h1 + ((size_t)e * B_ + bm) * (size_t)K_TOT; // ASRC==1
    const __nv_bfloat16* Wh =
        ((ASRC == 0) ? g_w1h : g_w2h) + (size_t)e * K_TOT * N_TOT + bn;
    const __nv_bfloat16* Wl =
        ((ASRC == 0) ? g_w1l : g_w2l) + (size_t)e * K_TOT * N_TOT + bn;
    const float* S  = g_s1 + e * K_TOT;
    const float* Tt = g_t1 + e * K_TOT;

    float acc[4][4][4];
    #pragma unroll
    for (int i = 0; i < 4; ++i)
        #pragma unroll
        for (int j = 0; j < 4; ++j)
            #pragma unroll
            for (int r = 0; r < 4; ++r) acc[i][j][r] = 0.f;

    constexpr int NT = K_TOT / 32;
    float4 av[4];   // ASRC==1 register staging

    // ---- prefetch stage 0
    if (ASRC == 0) {
        #pragma unroll
        for (int i = 0; i < 4; ++i) {
            int c = tid + i * 256, cc = c & 511;
            int row = cc >> 2, k4 = cc & 3;
            const __nv_bfloat16* src = ((c < 512) ? Ah : Al)
                                       + (size_t)row * K_TOT + k4 * 8;
            cp16(sb + ((c < 512) ? AH_(0) : AL_(0)) + row * 80 + k4 * 16, src);
        }
    } else {
        #pragma unroll
        for (int i = 0; i < 4; ++i) {
            int idx = tid + i * 256;
            av[i] = *(const float4*)(Af + (size_t)(idx >> 3) * K_TOT + (idx & 7) * 4);
        }
    }
    #pragma unroll
    for (int i = 0; i < 4; ++i) {
        int c = tid + i * 256, cc = c & 511;
        int kr = cc >> 4, n16 = cc & 15;
        const __nv_bfloat16* src = ((c < 512) ? Wh : Wl)
                                   + (size_t)kr * N_TOT + n16 * 8;
        cp16(sb + ((c < 512) ? BH_(0) : BL_(0)) + kr * 272 + n16 * 16, src);
    }
    cp_commit();

    for (int kt = 0; kt < NT; ++kt) {
        const int cur = kt & 1;

        if (ASRC == 1) {
            __nv_bfloat16* aH = (__nv_bfloat16*)(smem + AH_(cur));
            __nv_bfloat16* aL = (__nv_bfloat16*)(smem + AL_(cur));
            #pragma unroll
            for (int i = 0; i < 4; ++i) {
                int idx = tid + i * 256;
                int row = idx >> 3, c4 = (idx & 7) * 4;
                float4 v = av[i];
                int kc = kt * 32 + c4;
                float4 s4 = *(const float4*)(S + kc);
                float4 t4 = *(const float4*)(Tt + kc);
                v.x = fmaxf(0.f, fmaf(v.x, s4.x, t4.x));
                v.y = fmaxf(0.f, fmaf(v.y, s4.y, t4.y));
                v.z = fmaxf(0.f, fmaf(v.z, s4.z, t4.z));
                v.w = fmaxf(0.f, fmaf(v.w, s4.w, t4.w));
                uint32_t h0, l0, h1, l1;
                split_pair(v.x, v.y, h0, l0);
                split_pair(v.z, v.w, h1, l1);
                int off = row * ASTR + c4;
                *(uint32_t*)&aH[off]     = h0;
                *(uint32_t*)&aH[off + 2] = h1;
                *(uint32_t*)&aL[off]     = l0;
                *(uint32_t*)&aL[off + 2] = l1;
            }
        }

        cp_wait0();
        __syncthreads();

        // ---- prefetch stage kt+1
        if (kt + 1 < NT) {
            const int nxt = (kt + 1) & 1;
            const int k0n = (kt + 1) * 32;
            if (ASRC == 0) {
                #pragma unroll
                for (int i = 0; i < 4; ++i) {
                    int c = tid + i * 256, cc = c & 511;
                    int row = cc >> 2, k4 = cc & 3;
                    const __nv_bfloat16* src = ((c < 512) ? Ah : Al)
                        + (size_t)row * K_TOT + k0n + k4 * 8;
                    cp16(sb + ((c < 512) ? AH_(nxt) : AL_(nxt)) + row * 80 + k4 * 16, src);
                }
            } else {
                #pragma unroll
                for (int i = 0; i < 4; ++i) {
                    int idx = tid + i * 256;
                    av[i] = *(const float4*)(Af + (size_t)(idx >> 3) * K_TOT
                                               + k0n + (idx & 7) * 4);
                }
            }
            #pragma unroll
            for (int i = 0; i < 4; ++i) {
                int c = tid + i * 256, cc = c & 511;
                int kr = cc >> 4, n16 = cc & 15;
                const __nv_bfloat16* src = ((c < 512) ? Wh : Wl)
                    + (size_t)(k0n + kr) * N_TOT + n16 * 8;
                cp16(sb + ((c < 512) ? BH_(nxt) : BL_(nxt)) + kr * 272 + n16 * 16, src);
            }
            cp_commit();
        }

        // ---- MMAs on stage cur
        const __nv_bfloat16* aH = (const __nv_bfloat16*)(smem + AH_(cur));
        const __nv_bfloat16* aL = (const __nv_bfloat16*)(smem + AL_(cur));
        const __nv_bfloat16* bH = (const __nv_bfloat16*)(smem + BH_(cur));
        const __nv_bfloat16* bL = (const __nv_bfloat16*)(smem + BL_(cur));
        #pragma unroll
        for (int ks = 0; ks < 2; ++ks) {
            const int k0s = ks * 16;
            uint32_t bh[2][4], bl[2][4];
            #pragma unroll
            for (int g = 0; g < 2; ++g) {
                int r = k0s + (lane & 15);
                int c = wn + g * 16 + (lane >> 4) * 8;
                ldsm_x4t(bh[g], s2u(&bH[r * BSTR + c]));
                ldsm_x4t(bl[g], s2u(&bL[r * BSTR + c]));
            }
            #pragma unroll
            for (int mi = 0; mi < 4; ++mi) {
                uint32_t ah[4], al[4];
                int r = wm + mi * 16 + (lane & 15);
                int c = k0s + (lane >> 4) * 8;
                ldsm_x4(ah, s2u(&aH[r * ASTR + c]));
                ldsm_x4(al, s2u(&aL[r * ASTR + c]));
                #pragma unroll
                for (int ni = 0; ni < 4; ++ni) {
                    const uint32_t* ph = &bh[ni >> 1][(ni & 1) * 2];
                    const uint32_t* pl = &bl[ni >> 1][(ni & 1) * 2];
                    mma16816(acc[mi][ni], ah, ph);
                    mma16816(acc[mi][ni], ah, pl);
                    mma16816(acc[mi][ni], al, ph);
                }
            }
        }
        __syncthreads();
    }

    // ---- epilogue: +bias, store, fused BN stats (deterministic)
    float* C = ((ASRC == 0) ? g_h1 : g_h2) + ((size_t)e * B_ + bm) * N_TOT + bn;
    const float* bias = bias_all + e * N_TOT + bn;
    #pragma unroll
    for (int ni = 0; ni < 4; ++ni) {
        int c0 = wn + ni * 8 + (lane & 3) * 2;
        float b0 = bias[c0], b1 = bias[c0 + 1];
        float ss0 = 0.f, ss1 = 0.f, qq0 = 0.f, qq1 = 0.f;
        #pragma unroll
        for (int mi = 0; mi < 4; ++mi) {
            int r0 = wm + mi * 16 + (lane >> 2);
            float v00 = acc[mi][ni][0] + b0, v01 = acc[mi][ni][1] + b1;
            float v10 = acc[mi][ni][2] + b0, v11 = acc[mi][ni][3] + b1;
            float2 w0 = { v00, v01 }, w1 = { v10, v11 };
            *(float2*)(C + (size_t)r0 * N_TOT + c0) = w0;
            *(float2*)(C + (size_t)(r0 + 8) * N_TOT + c0) = w1;
            ss0 += v00 + v10;  ss1 += v01 + v11;
            qq0 += v00 * v00 + v10 * v10;
            qq1 += v01 * v01 + v11 * v11;
        }
        #pragma unroll
        for (int o = 4; o < 32; o <<= 1) {
            ss0 += __shfl_xor_sync(0xffffffffu, ss0, o);
            ss1 += __shfl_xor_sync(0xffffffffu, ss1, o);
            qq0 += __shfl_xor_sync(0xffffffffu, qq0, o);
            qq1 += __shfl_xor_sync(0xffffffffu, qq1, o);
        }
        if (lane < 4) {
            int c = wn + ni * 8 + lane * 2;
            int rg = wid & 1;
            sred_s[rg][c] = ss0; sred_s[rg][c + 1] = ss1;
            sred_q[rg][c] = qq0; sred_q[rg][c + 1] = qq1;
        }
    }
    __syncthreads();
    if (tid < 128) {
        float s = sred_s[0][tid] + sred_s[1][tid];
        float q = sred_q[0][tid] + sred_q[1][tid];
        size_t idx = ((size_t)e * N_TOT + bn + tid) * NSLAB + blockIdx.y;
        g_psum[idx] = s;
        g_psq[idx]  = q;
    }
}

// ---------------------------------------------------------------------------
// fp32 -> bf16 hi/lo split over a flat array
// ---------------------------------------------------------------------------
__global__ __launch_bounds__(256) void split_arr(
    const float* __restrict__ src, __nv_bfloat16* __restrict__ dh,
    __nv_bfloat16* __restrict__ dl, size_t n8)
{
    size_t i = (size_t)blockIdx.x * 256 + threadIdx.x;
    if (i >= n8) return;
    const float4* s = (const float4*)src + i * 2;
    float4 v0 = s[0], v1 = s[1];
    uint4 h, l;
    split_pair(v0.x, v0.y, h.x, l.x);
    split_pair(v0.z, v0.w, h.y, l.y);
    split_pair(v1.x, v1.y, h.z, l.z);
    split_pair(v1.z, v1.w, h.w, l.w);
    ((uint4*)dh)[i] = h;
    ((uint4*)dl)[i] = l;
}

// ---------------------------------------------------------------------------
// Gates: softmax_e( x . Wg[t] + bg[t] ); 4 rows per warp (Wg traffic /4).
// ---------------------------------------------------------------------------
__global__ __launch_bounds__(256) void gates_kernel(
    const float* __restrict__ X, const float* __restrict__ Wg,
    const float* __restrict__ bg)
{
    int warp = (blockIdx.x * blockDim.x + threadIdx.x) >> 5;
    int lane = threadIdx.x & 31;
    int r0 = warp * 4;
    if (r0 >= B_) return;
    const float* x0 = X + (size_t)(r0 + 0) * D_;
    const float* x1 = X + (size_t)(r0 + 1) * D_;
    const float* x2 = X + (size_t)(r0 + 2) * D_;
    const float* x3 = X + (size_t)(r0 + 3) * D_;

    float acc[4][16];
    #pragma unroll
    for (int r = 0; r < 4; ++r)
        #pragma unroll
        for (int i = 0; i < 16; ++i) acc[r][i] = 0.f;

    for (int d = lane; d < D_; d += 32) {
        float xv0 = x0[d], xv1 = x1[d], xv2 = x2[d], xv3 = x3[d];
        #pragma unroll
        for (int t = 0; t < T_; ++t) {
            const float* wr = Wg + ((size_t)t * D_ + d) * E_;
            float4 w0 = *(const float4*)wr;
            float4 w1 = *(const float4*)(wr + 4);
            float wv[8] = { w0.x, w0.y, w0.z, w0.w, w1.x, w1.y, w1.z, w1.w };
            #pragma unroll
            for (int ee = 0; ee < 8; ++ee) {
                acc[0][t*8+ee] = fmaf(xv0, wv[ee], acc[0][t*8+ee]);
                acc[1][t*8+ee] = fmaf(xv1, wv[ee], acc[1][t*8+ee]);
                acc[2][t*8+ee] = fmaf(xv2, wv[ee], acc[2][t*8+ee]);
                acc[3][t*8+ee] = fmaf(xv3, wv[ee], acc[3][t*8+ee]);
            }
        }
    }
    #pragma unroll
    for (int r = 0; r < 4; ++r)
        #pragma unroll
        for (int i = 0; i < 16; ++i)
            #pragma unroll
            for (int o = 16; o > 0; o >>= 1)
                acc[r][i] += __shfl_xor_sync(0xffffffffu, acc[r][i], o);

    if (lane < 4) {
        #pragma unroll
        for (int r = 0; r < 4; ++r) {
            if (lane == r) {
                #pragma unroll
                for (int t = 0; t < T_; ++t) {
                    float v[8], m = -1e30f;
                    #pragma unroll
                    for (int e = 0; e < 8; ++e) {
                        v[e] = acc[r][t*8+e] + bg[t*8+e];
                        m = fmaxf(m, v[e]);
                    }
                    float s = 0.f;
                    #pragma unroll
                    for (int e = 0; e < 8; ++e) { v[e] = expf(v[e] - m); s += v[e]; }
                    float inv = 1.f / s;
                    #pragma unroll
                    for (int e = 0; e < 8; ++e)
                        g_gates[((size_t)t * B_ + r0 + r) * E_ + e] = v[e] * inv;
                }
            }
        }
    }
}

// ---------------------------------------------------------------------------
// Combine per-mblock stats -> BN scale/shift (deterministic, 256 slabs)
// ---------------------------------------------------------------------------
__global__ __launch_bounds__(256) void stats_combine(
    int which, int Hc, const float* __restrict__ gamma,
    const float* __restrict__ beta)
{
    int i = blockIdx.x * 256 + threadIdx.x;
    if (i >= E_ * Hc) return;
    const float* ps = g_psum + (size_t)i * NSLAB;
    const float* pq = g_psq  + (size_t)i * NSLAB;
    float s = 0.f, q = 0.f;
    for (int j = 0; j < NSLAB; ++j) { s += ps[j]; q += pq[j]; }
    const float invB = 1.f / (float)B_;
    float mu  = s * invB;
    float var = q * invB - mu * mu;
    float inv = rsqrtf(var + 1e-5f);
    float gg = gamma[i], bb = beta[i];
    float* Sd = (which == 0) ? g_s1 : g_s2;
    float* Td = (which == 0) ? g_t1 : g_t2;
    Sd[i] = gg * inv;
    Td[i] = bb - gg * mu * inv;
}

// ---------------------------------------------------------------------------
// Final: out[t,b,e*H2+k] = relu(BN2(g_h2[e,b,k])) * gates[t,b,e]
// ---------------------------------------------------------------------------
__global__ __launch_bounds__(256) void final_kernel(float* __restrict__ out)
{
    size_t idx = (size_t)blockIdx.x * blockDim.x + threadIdx.x;
    int k4 = (int)(idx & 63);
    int b  = (int)((idx >> 6) & (B_ - 1));
    int e  = (int)(idx >> 21);
    int k  = k4 * 4;

    float4 h  = *(const float4*)(g_h2 + (((size_t)e * B_ + b) * H2_ + k));
    float4 s  = *(const float4*)(g_s2 + e * H2_ + k);
    float4 tt = *(const float4*)(g_t2 + e * H2_ + k);
    float4 y;
    y.x = fmaxf(0.f, fmaf(h.x, s.x, tt.x));
    y.y = fmaxf(0.f, fmaf(h.y, s.y, tt.y));
    y.z = fmaxf(0.f, fmaf(h.z, s.z, tt.z));
    y.w = fmaxf(0.f, fmaf(h.w, s.w, tt.w));

    float ga = g_gates[(size_t)b * E_ + e];
    float gb = g_gates[(size_t)B_ * E_ + (size_t)b * E_ + e];

    size_t o0 = (size_t)b * (E_ * H2_) + e * H2_ + k;
    size_t o1 = (size_t)B_ * (E_ * H2_) + o0;
    float4 v0 = { y.x * ga, y.y * ga, y.z * ga, y.w * ga };
    float4 v1 = { y.x * gb, y.y * gb, y.z * gb, y.w * gb };
    *(float4*)(out + o0) = v0;
    *(float4*)(out + o1) = v1;
}

// ---------------------------------------------------------------------------
extern "C" void kernel_launch(void* const* d_in, const int* in_sizes, int n_in,
                              void* d_out, int out_size)
{
    const float* x   = (const float*)d_in[0];
    const float* W1  = (const float*)d_in[1];
    const float* b1  = (const float*)d_in[2];
    const float* g1  = (const float*)d_in[3];
    const float* be1 = (const float*)d_in[4];
    const float* W2  = (const float*)d_in[5];
    const float* b2  = (const float*)d_in[6];
    const float* g2  = (const float*)d_in[7];
    const float* be2 = (const float*)d_in[8];
    const float* Wg  = (const float*)d_in[9];
    const float* bg  = (const float*)d_in[10];
    float* out = (float*)d_out;

    cudaFuncSetAttribute(gemm_hmma<D_, H1_, 0, 4>,
        cudaFuncAttributeMaxDynamicSharedMemorySize, SMEM_BYTES);
    cudaFuncSetAttribute(gemm_hmma<H1_, H2_, 1, 2>,
        cudaFuncAttributeMaxDynamicSharedMemorySize, SMEM_BYTES);

    // ---- pre-splits
    {
        __nv_bfloat16 *xh, *xl, *w1h, *w1l, *w2h, *w2l;
        cudaGetSymbolAddress((void**)&xh,  g_xh);
        cudaGetSymbolAddress((void**)&xl,  g_xl);
        cudaGetSymbolAddress((void**)&w1h, g_w1h);
        cudaGetSymbolAddress((void**)&w1l, g_w1l);
        cudaGetSymbolAddress((void**)&w2h, g_w2h);
        cudaGetSymbolAddress((void**)&w2l, g_w2l);
        size_t nx = (size_t)B_ * D_ / 8;
        size_t n1 = (size_t)E_ * D_ * H1_ / 8;
        size_t n2 = (size_t)E_ * H1_ * H2_ / 8;
        split_arr<<<(unsigned)((nx + 255) / 256), 256>>>(x,  xh,  xl,  nx);
        split_arr<<<(unsigned)((n1 + 255) / 256), 256>>>(W1, w1h, w1l, n1);
        split_arr<<<(unsigned)((n2 + 255) / 256), 256>>>(W2, w2h, w2l, n2);
    }

    gates_kernel<<<B_ / 32, 256>>>(x, Wg, bg);

    gemm_hmma<D_, H1_, 0, 4>
        <<<dim3(4 * E_, B_ / 128), 256, SMEM_BYTES>>>(b1);
    stats_combine<<<(E_ * H1_ + 255) / 256, 256>>>(0, H1_, g1, be1);

    gemm_hmma<H1_, H2_, 1, 2>
        <<<dim3(2 * E_, B_ / 128), 256, SMEM_BYTES>>>(b2);
    stats_combine<<<(E_ * H2_ + 255) / 256, 256>>>(1, H2_, g2, be2);

    final_kernel<<<(unsigned)((size_t)E_ * B_ * (H2_ / 4) / 256), 256>>>(out);
}

// round 6
// speedup vs baseline: 3.8376x; 1.3313x over previous
#include <cuda_runtime.h>
#include <cuda_fp16.h>
#include <cstdint>

#define B_   32768
#define D_   1472
#define E_   8
#define H1_  512
#define H2_  256
#define T_   2
#define NSLAB 256          // one stats slab per 128-row m-block

// ---------------- scratch (static device arrays; no cudaMalloc) ------------
__device__ float g_h1[(size_t)E_ * B_ * H1_];
__device__ float g_h2[(size_t)E_ * B_ * H2_];
__device__ float g_gates[(size_t)T_ * B_ * E_];
__device__ float g_psum[(size_t)E_ * H1_ * NSLAB];
__device__ float g_psq [(size_t)E_ * H1_ * NSLAB];
__device__ float g_s1[E_ * H1_], g_t1[E_ * H1_];
__device__ float g_s2[E_ * H2_], g_t2[E_ * H2_];
// fp16 pre-splits: x -> hi+lo pair; weights -> hi only
__device__ __half g_xh[(size_t)B_ * D_];
__device__ __half g_xl[(size_t)B_ * D_];
__device__ __half g_w1h[(size_t)E_ * D_ * H1_];
__device__ __half g_w2h[(size_t)E_ * H1_ * H2_];

// ---------------- PTX helpers ----------------------------------------------
__device__ __forceinline__ uint32_t s2u(const void* p) {
    return (uint32_t)__cvta_generic_to_shared(p);
}
__device__ __forceinline__ void ldsm_x4(uint32_t* r, uint32_t a) {
    asm volatile("ldmatrix.sync.aligned.m8n8.x4.shared.b16 {%0,%1,%2,%3}, [%4];"
        : "=r"(r[0]), "=r"(r[1]), "=r"(r[2]), "=r"(r[3]) : "r"(a));
}
__device__ __forceinline__ void ldsm_x4t(uint32_t* r, uint32_t a) {
    asm volatile("ldmatrix.sync.aligned.m8n8.x4.trans.shared.b16 {%0,%1,%2,%3}, [%4];"
        : "=r"(r[0]), "=r"(r[1]), "=r"(r[2]), "=r"(r[3]) : "r"(a));
}
__device__ __forceinline__ void mma16816(float* d, const uint32_t* a, const uint32_t* b) {
    asm volatile("mma.sync.aligned.m16n8k16.row.col.f32.f16.f16.f32 "
        "{%0,%1,%2,%3}, {%4,%5,%6,%7}, {%8,%9}, {%0,%1,%2,%3};"
        : "+f"(d[0]), "+f"(d[1]), "+f"(d[2]), "+f"(d[3])
        : "r"(a[0]), "r"(a[1]), "r"(a[2]), "r"(a[3]), "r"(b[0]), "r"(b[1]));
}
__device__ __forceinline__ void cp16(uint32_t dst, const void* src) {
    asm volatile("cp.async.cg.shared.global [%0], [%1], 16;"
        :: "r"(dst), "l"(src) : "memory");
}
__device__ __forceinline__ void cp_commit() {
    asm volatile("cp.async.commit_group;" ::: "memory");
}
__device__ __forceinline__ void cp_wait0() {
    asm volatile("cp.async.wait_group 0;" ::: "memory");
}

// fp32 -> fp16 hi + fp16 residual lo, packed pairs
__device__ __forceinline__ void split_pair_h(float x, float y,
                                             uint32_t& hi, uint32_t& lo) {
    __half hx = __float2half_rn(x);
    __half hy = __float2half_rn(y);
    __half lx = __float2half_rn(x - __half2float(hx));
    __half ly = __float2half_rn(y - __half2float(hy));
    __half2 h = __halves2half2(hx, hy);
    __half2 l = __halves2half2(lx, ly);
    hi = *reinterpret_cast<uint32_t*>(&h);
    lo = *reinterpret_cast<uint32_t*>(&l);
}

// ---------------- SMEM layout (bytes) ---------------------------------------
// A tiles: 128 rows x 32 fp16, padded row = 40 elems (80 B)  -> 10240 B each
// B tile : 32 rows x 128 fp16, padded row = 136 elems (272B) ->  8704 B
#define ASTR 40
#define BSTR 136
#define STG_SZ 29184
#define AH_(b) ((b) * STG_SZ)
#define AL_(b) ((b) * STG_SZ + 10240)
#define BH_(b) ((b) * STG_SZ + 20480)
#define SMEM_BYTES (2 * STG_SZ)   // 58368 -> 2 CTAs/SM

// ---------------------------------------------------------------------------
// fp16 2-product HMMA GEMM: D = (ah+al)*bh, double-buffered cp.async,
// 2 CTAs/SM, warp tile m32 x n64 (minimal ldsm bytes), fused BN stats.
// ---------------------------------------------------------------------------
template<int K_TOT, int N_TOT, int ASRC, int NB>
__global__ __launch_bounds__(256, 2) void gemm_hmma(
    const float* __restrict__ bias_all)
{
    extern __shared__ char smem[];
    __shared__ float sred_s[4][128];
    __shared__ float sred_q[4][128];
    const uint32_t sb = s2u(smem);
    const int tid  = threadIdx.x;
    const int lane = tid & 31;
    const int wid  = tid >> 5;
    const int wm   = (wid & 3) * 32;   // 4 warp rows of 32
    const int wn   = (wid >> 2) * 64;  // 2 warp cols of 64

    const int e  = blockIdx.x / NB;
    const int bn = (blockIdx.x % NB) * 128;
    const int bm = blockIdx.y * 128;

    const __half* Ah = g_xh + (size_t)bm * K_TOT;                   // ASRC==0
    const __half* Al = g_xl + (size_t)bm * K_TOT;
    const float* Af = g_h1 + ((size_t)e * B_ + bm) * (size_t)K_TOT; // ASRC==1
    const __half* Wh =
        ((ASRC == 0) ? g_w1h : g_w2h) + (size_t)e * K_TOT * N_TOT + bn;
    const float* S  = g_s1 + e * K_TOT;
    const float* Tt = g_t1 + e * K_TOT;

    float acc[2][8][4];
    #pragma unroll
    for (int i = 0; i < 2; ++i)
        #pragma unroll
        for (int j = 0; j < 8; ++j)
            #pragma unroll
            for (int r = 0; r < 4; ++r) acc[i][j][r] = 0.f;

    constexpr int NT = K_TOT / 32;
    float4 av[4];   // ASRC==1 register staging

    // ---- prefetch stage 0
    if (ASRC == 0) {
        #pragma unroll
        for (int i = 0; i < 4; ++i) {
            int c = tid + i * 256, cc = c & 511;
            int row = cc >> 2, k4 = cc & 3;
            const __half* src = ((c < 512) ? Ah : Al)
                                + (size_t)row * K_TOT + k4 * 8;
            cp16(sb + ((c < 512) ? AH_(0) : AL_(0)) + row * 80 + k4 * 16, src);
        }
    } else {
        #pragma unroll
        for (int i = 0; i < 4; ++i) {
            int idx = tid + i * 256;
            av[i] = *(const float4*)(Af + (size_t)(idx >> 3) * K_TOT + (idx & 7) * 4);
        }
    }
    #pragma unroll
    for (int i = 0; i < 2; ++i) {
        int cc = tid + i * 256;
        int kr = cc >> 4, n16 = cc & 15;
        cp16(sb + BH_(0) + kr * 272 + n16 * 16,
             Wh + (size_t)kr * N_TOT + n16 * 8);
    }
    cp_commit();

    for (int kt = 0; kt < NT; ++kt) {
        const int cur = kt & 1;

        if (ASRC == 1) {
            __half* aH = (__half*)(smem + AH_(cur));
            __half* aL = (__half*)(smem + AL_(cur));
            #pragma unroll
            for (int i = 0; i < 4; ++i) {
                int idx = tid + i * 256;
                int row = idx >> 3, c4 = (idx & 7) * 4;
                float4 v = av[i];
                int kc = kt * 32 + c4;
                float4 s4 = *(const float4*)(S + kc);
                float4 t4 = *(const float4*)(Tt + kc);
                v.x = fmaxf(0.f, fmaf(v.x, s4.x, t4.x));
                v.y = fmaxf(0.f, fmaf(v.y, s4.y, t4.y));
                v.z = fmaxf(0.f, fmaf(v.z, s4.z, t4.z));
                v.w = fmaxf(0.f, fmaf(v.w, s4.w, t4.w));
                uint32_t h0, l0, h1, l1;
                split_pair_h(v.x, v.y, h0, l0);
                split_pair_h(v.z, v.w, h1, l1);
                int off = row * ASTR + c4;
                *(uint32_t*)&aH[off]     = h0;
                *(uint32_t*)&aH[off + 2] = h1;
                *(uint32_t*)&aL[off]     = l0;
                *(uint32_t*)&aL[off + 2] = l1;
            }
        }

        cp_wait0();
        __syncthreads();

        // ---- prefetch stage kt+1
        if (kt + 1 < NT) {
            const int nxt = (kt + 1) & 1;
            const int k0n = (kt + 1) * 32;
            if (ASRC == 0) {
                #pragma unroll
                for (int i = 0; i < 4; ++i) {
                    int c = tid + i * 256, cc = c & 511;
                    int row = cc >> 2, k4 = cc & 3;
                    const __half* src = ((c < 512) ? Ah : Al)
                        + (size_t)row * K_TOT + k0n + k4 * 8;
                    cp16(sb + ((c < 512) ? AH_(nxt) : AL_(nxt)) + row * 80 + k4 * 16, src);
                }
            } else {
                #pragma unroll
                for (int i = 0; i < 4; ++i) {
                    int idx = tid + i * 256;
                    av[i] = *(const float4*)(Af + (size_t)(idx >> 3) * K_TOT
                                               + k0n + (idx & 7) * 4);
                }
            }
            #pragma unroll
            for (int i = 0; i < 2; ++i) {
                int cc = tid + i * 256;
                int kr = cc >> 4, n16 = cc & 15;
                cp16(sb + BH_(nxt) + kr * 272 + n16 * 16,
                     Wh + (size_t)(k0n + kr) * N_TOT + n16 * 8);
            }
            cp_commit();
        }

        // ---- MMAs on stage cur
        const __half* aH = (const __half*)(smem + AH_(cur));
        const __half* aL = (const __half*)(smem + AL_(cur));
        const __half* bH = (const __half*)(smem + BH_(cur));
        #pragma unroll
        for (int ks = 0; ks < 2; ++ks) {
            const int k0s = ks * 16;
            uint32_t bh[4][4];
            #pragma unroll
            for (int g = 0; g < 4; ++g) {
                int r = k0s + (lane & 15);
                int c = wn + g * 16 + (lane >> 4) * 8;
                ldsm_x4t(bh[g], s2u(&bH[r * BSTR + c]));
            }
            #pragma unroll
            for (int mi = 0; mi < 2; ++mi) {
                uint32_t ah[4], al[4];
                int r = wm + mi * 16 + (lane & 15);
                int c = k0s + (lane >> 4) * 8;
                ldsm_x4(ah, s2u(&aH[r * ASTR + c]));
                ldsm_x4(al, s2u(&aL[r * ASTR + c]));
                #pragma unroll
                for (int ni = 0; ni < 8; ++ni) {
                    const uint32_t* pb = &bh[ni >> 1][(ni & 1) * 2];
                    mma16816(acc[mi][ni], ah, pb);
                    mma16816(acc[mi][ni], al, pb);
                }
            }
        }
        __syncthreads();
    }

    // ---- epilogue: +bias, store, fused BN stats (deterministic)
    float* C = ((ASRC == 0) ? g_h1 : g_h2) + ((size_t)e * B_ + bm) * N_TOT + bn;
    const float* bias = bias_all + e * N_TOT + bn;
    #pragma unroll
    for (int ni = 0; ni < 8; ++ni) {
        int c0 = wn + ni * 8 + (lane & 3) * 2;
        float b0 = bias[c0], b1 = bias[c0 + 1];
        float ss0 = 0.f, ss1 = 0.f, qq0 = 0.f, qq1 = 0.f;
        #pragma unroll
        for (int mi = 0; mi < 2; ++mi) {
            int r0 = wm + mi * 16 + (lane >> 2);
            float v00 = acc[mi][ni][0] + b0, v01 = acc[mi][ni][1] + b1;
            float v10 = acc[mi][ni][2] + b0, v11 = acc[mi][ni][3] + b1;
            float2 w0 = { v00, v01 }, w1 = { v10, v11 };
            *(float2*)(C + (size_t)r0 * N_TOT + c0) = w0;
            *(float2*)(C + (size_t)(r0 + 8) * N_TOT + c0) = w1;
            ss0 += v00 + v10;  ss1 += v01 + v11;
            qq0 += v00 * v00 + v10 * v10;
            qq1 += v01 * v01 + v11 * v11;
        }
        #pragma unroll
        for (int o = 4; o < 32; o <<= 1) {
            ss0 += __shfl_xor_sync(0xffffffffu, ss0, o);
            ss1 += __shfl_xor_sync(0xffffffffu, ss1, o);
            qq0 += __shfl_xor_sync(0xffffffffu, qq0, o);
            qq1 += __shfl_xor_sync(0xffffffffu, qq1, o);
        }
        if (lane < 4) {
            int c = wn + ni * 8 + lane * 2;
            int rg = wid & 3;
            sred_s[rg][c] = ss0; sred_s[rg][c + 1] = ss1;
            sred_q[rg][c] = qq0; sred_q[rg][c + 1] = qq1;
        }
    }
    __syncthreads();
    if (tid < 128) {
        float s = sred_s[0][tid] + sred_s[1][tid] + sred_s[2][tid] + sred_s[3][tid];
        float q = sred_q[0][tid] + sred_q[1][tid] + sred_q[2][tid] + sred_q[3][tid];
        size_t idx = ((size_t)e * N_TOT + bn + tid) * NSLAB + blockIdx.y;
        g_psum[idx] = s;
        g_psq[idx]  = q;
    }
}

// ---------------------------------------------------------------------------
// fp32 -> fp16 hi/lo split (x) and fp32 -> fp16 round (weights)
// ---------------------------------------------------------------------------
__global__ __launch_bounds__(256) void split_f16(
    const float* __restrict__ src, __half* __restrict__ dh,
    __half* __restrict__ dl, size_t n8)
{
    size_t i = (size_t)blockIdx.x * 256 + threadIdx.x;
    if (i >= n8) return;
    const float4* s = (const float4*)src + i * 2;
    float4 v0 = s[0], v1 = s[1];
    uint4 h, l;
    split_pair_h(v0.x, v0.y, h.x, l.x);
    split_pair_h(v0.z, v0.w, h.y, l.y);
    split_pair_h(v1.x, v1.y, h.z, l.z);
    split_pair_h(v1.z, v1.w, h.w, l.w);
    ((uint4*)dh)[i] = h;
    ((uint4*)dl)[i] = l;
}

__global__ __launch_bounds__(256) void round_f16(
    const float* __restrict__ src, __half* __restrict__ dh, size_t n8)
{
    size_t i = (size_t)blockIdx.x * 256 + threadIdx.x;
    if (i >= n8) return;
    const float4* s = (const float4*)src + i * 2;
    float4 v0 = s[0], v1 = s[1];
    __half2 h0 = __floats2half2_rn(v0.x, v0.y);
    __half2 h1 = __floats2half2_rn(v0.z, v0.w);
    __half2 h2 = __floats2half2_rn(v1.x, v1.y);
    __half2 h3 = __floats2half2_rn(v1.z, v1.w);
    uint4 h = { *(uint32_t*)&h0, *(uint32_t*)&h1, *(uint32_t*)&h2, *(uint32_t*)&h3 };
    ((uint4*)dh)[i] = h;
}

// ---------------------------------------------------------------------------
// Gates: softmax_e( x . Wg[t] + bg[t] ); 4 rows per warp, float4 X loads.
// ---------------------------------------------------------------------------
__global__ __launch_bounds__(256) void gates_kernel(
    const float* __restrict__ X, const float* __restrict__ Wg,
    const float* __restrict__ bg)
{
    int warp = (blockIdx.x * blockDim.x + threadIdx.x) >> 5;
    int lane = threadIdx.x & 31;
    int r0 = warp * 4;
    if (r0 >= B_) return;
    const float* x0 = X + (size_t)(r0 + 0) * D_;
    const float* x1 = X + (size_t)(r0 + 1) * D_;
    const float* x2 = X + (size_t)(r0 + 2) * D_;
    const float* x3 = X + (size_t)(r0 + 3) * D_;

    float acc[4][16];
    #pragma unroll
    for (int r = 0; r < 4; ++r)
        #pragma unroll
        for (int i = 0; i < 16; ++i) acc[r][i] = 0.f;

    for (int d0 = lane * 4; d0 < D_; d0 += 128) {
        float4 xv[4];
        xv[0] = *(const float4*)(x0 + d0);
        xv[1] = *(const float4*)(x1 + d0);
        xv[2] = *(const float4*)(x2 + d0);
        xv[3] = *(const float4*)(x3 + d0);
        #pragma unroll
        for (int j = 0; j < 4; ++j) {
            int d = d0 + j;
            float xj[4] = { ((const float*)&xv[0])[j], ((const float*)&xv[1])[j],
                            ((const float*)&xv[2])[j], ((const float*)&xv[3])[j] };
            #pragma unroll
            for (int t = 0; t < T_; ++t) {
                const float* wr = Wg + ((size_t)t * D_ + d) * E_;
                float4 w0 = *(const float4*)wr;
                float4 w1 = *(const float4*)(wr + 4);
                float wv[8] = { w0.x, w0.y, w0.z, w0.w, w1.x, w1.y, w1.z, w1.w };
                #pragma unroll
                for (int ee = 0; ee < 8; ++ee) {
                    acc[0][t*8+ee] = fmaf(xj[0], wv[ee], acc[0][t*8+ee]);
                    acc[1][t*8+ee] = fmaf(xj[1], wv[ee], acc[1][t*8+ee]);
                    acc[2][t*8+ee] = fmaf(xj[2], wv[ee], acc[2][t*8+ee]);
                    acc[3][t*8+ee] = fmaf(xj[3], wv[ee], acc[3][t*8+ee]);
                }
            }
        }
    }
    #pragma unroll
    for (int r = 0; r < 4; ++r)
        #pragma unroll
        for (int i = 0; i < 16; ++i)
            #pragma unroll
            for (int o = 16; o > 0; o >>= 1)
                acc[r][i] += __shfl_xor_sync(0xffffffffu, acc[r][i], o);

    if (lane < 4) {
        #pragma unroll
        for (int r = 0; r < 4; ++r) {
            if (lane == r) {
                #pragma unroll
                for (int t = 0; t < T_; ++t) {
                    float v[8], m = -1e30f;
                    #pragma unroll
                    for (int e = 0; e < 8; ++e) {
                        v[e] = acc[r][t*8+e] + bg[t*8+e];
                        m = fmaxf(m, v[e]);
                    }
                    float s = 0.f;
                    #pragma unroll
                    for (int e = 0; e < 8; ++e) { v[e] = expf(v[e] - m); s += v[e]; }
                    float inv = 1.f / s;
                    #pragma unroll
                    for (int e = 0; e < 8; ++e)
                        g_gates[((size_t)t * B_ + r0 + r) * E_ + e] = v[e] * inv;
                }
            }
        }
    }
}

// ---------------------------------------------------------------------------
// Combine per-mblock stats -> BN scale/shift (deterministic, 256 slabs)
// ---------------------------------------------------------------------------
__global__ __launch_bounds__(256) void stats_combine(
    int which, int Hc, const float* __restrict__ gamma,
    const float* __restrict__ beta)
{
    int i = blockIdx.x * 256 + threadIdx.x;
    if (i >= E_ * Hc) return;
    const float* ps = g_psum + (size_t)i * NSLAB;
    const float* pq = g_psq  + (size_t)i * NSLAB;
    float s = 0.f, q = 0.f;
    for (int j = 0; j < NSLAB; ++j) { s += ps[j]; q += pq[j]; }
    const float invB = 1.f / (float)B_;
    float mu  = s * invB;
    float var = q * invB - mu * mu;
    float inv = rsqrtf(var + 1e-5f);
    float gg = gamma[i], bb = beta[i];
    float* Sd = (which == 0) ? g_s1 : g_s2;
    float* Td = (which == 0) ? g_t1 : g_t2;
    Sd[i] = gg * inv;
    Td[i] = bb - gg * mu * inv;
}

// ---------------------------------------------------------------------------
// Final: out[t,b,e*H2+k] = relu(BN2(g_h2[e,b,k])) * gates[t,b,e]
// ---------------------------------------------------------------------------
__global__ __launch_bounds__(256) void final_kernel(float* __restrict__ out)
{
    size_t idx = (size_t)blockIdx.x * blockDim.x + threadIdx.x;
    int k4 = (int)(idx & 63);
    int b  = (int)((idx >> 6) & (B_ - 1));
    int e  = (int)(idx >> 21);
    int k  = k4 * 4;

    float4 h  = *(const float4*)(g_h2 + (((size_t)e * B_ + b) * H2_ + k));
    float4 s  = *(const float4*)(g_s2 + e * H2_ + k);
    float4 tt = *(const float4*)(g_t2 + e * H2_ + k);
    float4 y;
    y.x = fmaxf(0.f, fmaf(h.x, s.x, tt.x));
    y.y = fmaxf(0.f, fmaf(h.y, s.y, tt.y));
    y.z = fmaxf(0.f, fmaf(h.z, s.z, tt.z));
    y.w = fmaxf(0.f, fmaf(h.w, s.w, tt.w));

    float ga = g_gates[(size_t)b * E_ + e];
    float gb = g_gates[(size_t)B_ * E_ + (size_t)b * E_ + e];

    size_t o0 = (size_t)b * (E_ * H2_) + e * H2_ + k;
    size_t o1 = (size_t)B_ * (E_ * H2_) + o0;
    float4 v0 = { y.x * ga, y.y * ga, y.z * ga, y.w * ga };
    float4 v1 = { y.x * gb, y.y * gb, y.z * gb, y.w * gb };
    *(float4*)(out + o0) = v0;
    *(float4*)(out + o1) = v1;
}

// ---------------------------------------------------------------------------
extern "C" void kernel_launch(void* const* d_in, const int* in_sizes, int n_in,
                              void* d_out, int out_size)
{
    const float* x   = (const float*)d_in[0];
    const float* W1  = (const float*)d_in[1];
    const float* b1  = (const float*)d_in[2];
    const float* g1  = (const float*)d_in[3];
    const float* be1 = (const float*)d_in[4];
    const float* W2  = (const float*)d_in[5];
    const float* b2  = (const float*)d_in[6];
    const float* g2  = (const float*)d_in[7];
    const float* be2 = (const float*)d_in[8];
    const float* Wg  = (const float*)d_in[9];
    const float* bg  = (const float*)d_in[10];
    float* out = (float*)d_out;

    cudaFuncSetAttribute(gemm_hmma<D_, H1_, 0, 4>,
        cudaFuncAttributeMaxDynamicSharedMemorySize, SMEM_BYTES);
    cudaFuncSetAttribute(gemm_hmma<H1_, H2_, 1, 2>,
        cudaFuncAttributeMaxDynamicSharedMemorySize, SMEM_BYTES);

    // ---- pre-splits / rounds
    {
        __half *xh, *xl, *w1h, *w2h;
        cudaGetSymbolAddress((void**)&xh,  g_xh);
        cudaGetSymbolAddress((void**)&xl,  g_xl);
        cudaGetSymbolAddress((void**)&w1h, g_w1h);
        cudaGetSymbolAddress((void**)&w2h, g_w2h);
        size_t nx = (size_t)B_ * D_ / 8;
        size_t n1 = (size_t)E_ * D_ * H1_ / 8;
        size_t n2 = (size_t)E_ * H1_ * H2_ / 8;
        split_f16<<<(unsigned)((nx + 255) / 256), 256>>>(x, xh, xl, nx);
        round_f16<<<(unsigned)((n1 + 255) / 256), 256>>>(W1, w1h, n1);
        round_f16<<<(unsigned)((n2 + 255) / 256), 256>>>(W2, w2h, n2);
    }

    gates_kernel<<<B_ / 32, 256>>>(x, Wg, bg);

    gemm_hmma<D_, H1_, 0, 4>
        <<<dim3(4 * E_, B_ / 128), 256, SMEM_BYTES>>>(b1);
    stats_combine<<<(E_ * H1_ + 255) / 256, 256>>>(0, H1_, g1, be1);

    gemm_hmma<H1_, H2_, 1, 2>
        <<<dim3(2 * E_, B_ / 128), 256, SMEM_BYTES>>>(b2);
    stats_combine<<<(E_ * H2_ + 255) / 256, 256>>>(1, H2_, g2, be2);

    final_kernel<<<(unsigned)((size_t)E_ * B_ * (H2_ / 4) / 256), 256>>>(out);
}